// round 5
// baseline (speedup 1.0000x reference)
#include <cuda_runtime.h>
#include <cuda_bf16.h>

#define D     64
#define DE    16
#define HDIM  128
#define DOUT  64
#define MAXN  100000
#define MAXE  1600000
#define TE    64

// Scratch (device globals — allocation-free contract)
__device__ float g_P[(size_t)MAXN * HDIM];    // X @ We1[0:64]  + be1
__device__ float g_Q[(size_t)MAXN * HDIM];    // X @ We1[64:128]
__device__ float g_agg[(size_t)MAXN * DOUT];  // segment sum

__device__ __forceinline__ float siluf(float x) {
    return __fdividef(x, 1.0f + __expf(-x));
}
__device__ __forceinline__ float sigmoidf_(float x) {
    return __fdividef(1.0f, 1.0f + __expf(-x));
}

// ---------------------------------------------------------------- zero agg
__global__ void zero_agg_kernel(long long n4) {
    long long i = (long long)blockIdx.x * blockDim.x + threadIdx.x;
    const long long stride = (long long)gridDim.x * blockDim.x;
    float4* p = (float4*)g_agg;
    const float4 z = make_float4(0.f, 0.f, 0.f, 0.f);
    for (; i < n4; i += stride) p[i] = z;
}

// ---------------------------------------------------- P/Q precompute (8 nodes/block)
#define PNODES 8
__global__ __launch_bounds__(128) void precompute_kernel(
    const float* __restrict__ X, const float* __restrict__ We1,
    const float* __restrict__ be1, int N)
{
    __shared__ float x_sh[PNODES][D];
    const int t = threadIdx.x;           // 0..127 -> output hidden unit
    const int nb = blockIdx.x * PNODES;

    for (int idx = t; idx < PNODES * D; idx += 128) {
        const int m = idx >> 6, k = idx & 63;
        const int n = nb + m;
        x_sh[m][k] = (n < N) ? X[(long long)n * D + k] : 0.f;
    }
    __syncthreads();

    const float b = be1[t];
    float p[PNODES], q[PNODES];
#pragma unroll
    for (int m = 0; m < PNODES; m++) { p[m] = b; q[m] = 0.f; }

#pragma unroll 4
    for (int k = 0; k < D; k++) {
        const float w1 = We1[k * HDIM + t];
        const float w2 = We1[(D + k) * HDIM + t];
#pragma unroll
        for (int m = 0; m < PNODES; m++) {
            const float xv = x_sh[m][k];
            p[m] += xv * w1;
            q[m] += xv * w2;
        }
    }
#pragma unroll
    for (int m = 0; m < PNODES; m++) {
        const int n = nb + m;
        if (n < N) {
            g_P[(long long)n * HDIM + t] = p[m];
            g_Q[(long long)n * HDIM + t] = q[m];
        }
    }
}

// ---------------------------------------------------------------- fused edge kernel
// Phase 1 (warp-per-edge): a = silu(P[i] + Q[j] + e@W1c) -> shared tile [64][128]
//                          attn = sigmoid(|h_i - h_j| @ Wa + ba)
// Phase 2 (block GEMM 64x64x128): m = silu(a @ We2 + be2) * attn -> atomic scatter
__global__ __launch_bounds__(256, 2) void edge_kernel(
    const float* __restrict__ X, const int* __restrict__ ei,
    const float* __restrict__ EF, const float* __restrict__ We1,
    const float* __restrict__ We2, const float* __restrict__ be2,
    const float* __restrict__ Wa, const float* __restrict__ ba,
    int N, int E)
{
    __shared__ float A_sh[TE][HDIM + 2];
    __shared__ float attn_sh[TE];
    __shared__ int   fi_sh[TE];

    const int tid  = threadIdx.x;
    const int lane = tid & 31;
    const int warp = tid >> 5;   // 0..7

    // W1c slice held in registers, reused across all edges of this block
    float w1c[DE][4];
#pragma unroll
    for (int k = 0; k < DE; k++)
#pragma unroll
        for (int c = 0; c < 4; c++)
            w1c[k][c] = We1[(2 * D + k) * HDIM + lane + 32 * c];

    const float wa0 = Wa[lane];
    const float wa1 = Wa[lane + 32];
    const float ba0 = ba[0];

    const int numTiles = (E + TE - 1) / TE;
    for (int tile = blockIdx.x; tile < numTiles; tile += gridDim.x) {
        const int base = tile * TE;

        // -------- phase 1: each warp computes layer-1 for 8 edges --------
        for (int s = 0; s < 8; s++) {
            const int eL = warp * 8 + s;
            const int e  = base + eL;
            float a0 = 0.f, a1 = 0.f, a2 = 0.f, a3 = 0.f;
            if (e < E) {
                const int iN = ei[e];
                const int jN = ei[E + e];
                const float* Pi = g_P + (long long)iN * HDIM;
                const float* Qj = g_Q + (long long)jN * HDIM;
                a0 = Pi[lane]      + Qj[lane];
                a1 = Pi[lane + 32] + Qj[lane + 32];
                a2 = Pi[lane + 64] + Qj[lane + 64];
                a3 = Pi[lane + 96] + Qj[lane + 96];
                const float* efp = EF + (long long)e * DE;
#pragma unroll
                for (int k = 0; k < DE; k++) {
                    const float ef = __ldg(efp + k);
                    a0 += ef * w1c[k][0];
                    a1 += ef * w1c[k][1];
                    a2 += ef * w1c[k][2];
                    a3 += ef * w1c[k][3];
                }
                a0 = siluf(a0); a1 = siluf(a1); a2 = siluf(a2); a3 = siluf(a3);

                // attention gate
                const float* Xi = X + (long long)iN * D;
                const float* Xj = X + (long long)jN * D;
                float p = fabsf(Xi[lane] - Xj[lane]) * wa0
                        + fabsf(Xi[lane + 32] - Xj[lane + 32]) * wa1;
#pragma unroll
                for (int off = 16; off > 0; off >>= 1)
                    p += __shfl_down_sync(0xffffffffu, p, off);
                if (lane == 0) {
                    attn_sh[eL] = sigmoidf_(p + ba0);
                    fi_sh[eL]   = iN;
                }
            } else if (lane == 0) {
                attn_sh[eL] = 0.f;
                fi_sh[eL]   = 0;
            }
            A_sh[eL][lane]      = a0;
            A_sh[eL][lane + 32] = a1;
            A_sh[eL][lane + 64] = a2;
            A_sh[eL][lane + 96] = a3;
        }
        __syncthreads();

        // -------- phase 2: 64x64 GEMM tile, 4x4 micro-tile per thread --------
        const int tx = tid & 15;   // outputs 4*tx .. 4*tx+3
        const int ty = tid >> 4;   // edges   4*ty .. 4*ty+3
        float r[4][4];
#pragma unroll
        for (int m = 0; m < 4; m++)
#pragma unroll
            for (int u = 0; u < 4; u++) r[m][u] = 0.f;

#pragma unroll 4
        for (int k = 0; k < HDIM; k++) {
            const float4 w = *(const float4*)(We2 + k * DOUT + 4 * tx);
            const float a0 = A_sh[4 * ty + 0][k];
            const float a1 = A_sh[4 * ty + 1][k];
            const float a2 = A_sh[4 * ty + 2][k];
            const float a3 = A_sh[4 * ty + 3][k];
            r[0][0] += a0 * w.x; r[0][1] += a0 * w.y; r[0][2] += a0 * w.z; r[0][3] += a0 * w.w;
            r[1][0] += a1 * w.x; r[1][1] += a1 * w.y; r[1][2] += a1 * w.z; r[1][3] += a1 * w.w;
            r[2][0] += a2 * w.x; r[2][1] += a2 * w.y; r[2][2] += a2 * w.z; r[2][3] += a2 * w.w;
            r[3][0] += a3 * w.x; r[3][1] += a3 * w.y; r[3][2] += a3 * w.z; r[3][3] += a3 * w.w;
        }

        const float4 b2 = *(const float4*)(be2 + 4 * tx);
#pragma unroll
        for (int m = 0; m < 4; m++) {
            const int eL = 4 * ty + m;
            if (base + eL < E) {
                const float at = attn_sh[eL];
                float* aggp = g_agg + (long long)fi_sh[eL] * DOUT + 4 * tx;
                atomicAdd(aggp + 0, siluf(r[m][0] + b2.x) * at);
                atomicAdd(aggp + 1, siluf(r[m][1] + b2.y) * at);
                atomicAdd(aggp + 2, siluf(r[m][2] + b2.z) * at);
                atomicAdd(aggp + 3, siluf(r[m][3] + b2.w) * at);
            }
        }
        __syncthreads();
    }
}

// ---------------------------------------------------------------- node MLP
__global__ __launch_bounds__(128) void node_kernel(
    const float* __restrict__ X, const float* __restrict__ Wn1,
    const float* __restrict__ bn1, const float* __restrict__ Wn2,
    const float* __restrict__ bn2, float* __restrict__ out, int N)
{
    const int n = blockIdx.x;
    if (n >= N) return;
    __shared__ float in_sh[HDIM];
    __shared__ float hid_sh[HDIM];
    const int t = threadIdx.x;

    if (t < D) in_sh[t] = X[(long long)n * D + t];
    else       in_sh[t] = g_agg[(long long)n * DOUT + (t - D)];
    __syncthreads();

    float h = bn1[t];
#pragma unroll 8
    for (int k = 0; k < HDIM; k++) h += in_sh[k] * Wn1[k * HDIM + t];
    hid_sh[t] = siluf(h);
    __syncthreads();

    if (t < DOUT) {
        float o = bn2[t];
#pragma unroll 8
        for (int k = 0; k < HDIM; k++) o += hid_sh[k] * Wn2[k * DOUT + t];
        out[(long long)n * DOUT + t] = o;
    }
}

// ---------------------------------------------------------------- tail copies
__global__ void tail_kernel(const int* __restrict__ ei,
                            const float* __restrict__ EF,
                            float* __restrict__ out,
                            long long offEI, long long nEI, long long nEF)
{
    long long idx = (long long)blockIdx.x * blockDim.x + threadIdx.x;
    const long long stride = (long long)gridDim.x * blockDim.x;
    for (long long i = idx; i < nEI; i += stride)
        out[offEI + i] = (float)ei[i];
    const long long offEF = offEI + nEI;
    for (long long i = idx; i < nEF; i += stride)
        out[offEF + i] = EF[i];
}

// ---------------------------------------------------------------- launch
extern "C" void kernel_launch(void* const* d_in, const int* in_sizes, int n_in,
                              void* d_out, int out_size)
{
    const float* X   = (const float*)d_in[0];
    const int*   ei  = (const int*)d_in[1];
    const float* EF  = (const float*)d_in[2];
    const float* We1 = (const float*)d_in[3];
    const float* be1 = (const float*)d_in[4];
    const float* We2 = (const float*)d_in[5];
    const float* be2 = (const float*)d_in[6];
    const float* Wa  = (const float*)d_in[7];
    const float* ba  = (const float*)d_in[8];
    const float* Wn1 = (const float*)d_in[9];
    const float* bn1 = (const float*)d_in[10];
    const float* Wn2 = (const float*)d_in[11];
    const float* bn2 = (const float*)d_in[12];

    const int N = in_sizes[0] / D;
    const int E = in_sizes[2] / DE;
    float* out = (float*)d_out;

    zero_agg_kernel<<<512, 256>>>(((long long)N * DOUT) / 4);
    precompute_kernel<<<(N + PNODES - 1) / PNODES, 128>>>(X, We1, be1, N);
    edge_kernel<<<1216, 256>>>(X, ei, EF, We1, We2, be2, Wa, ba, N, E);
    node_kernel<<<N, 128>>>(X, Wn1, bn1, Wn2, bn2, out, N);

    const long long n64 = (long long)N * DOUT;
    long long avail = (long long)out_size - n64;
    if (avail > 0) {
        long long nEI = 2LL * E;
        if (nEI > avail) nEI = avail;
        long long nEF = avail - nEI;
        const long long maxEF = (long long)E * DE;
        if (nEF > maxEF) nEF = maxEF;
        tail_kernel<<<4096, 256>>>(ei, EF, out, n64, nEI, nEF);
    }
}

// round 7
// speedup vs baseline: 1.1917x; 1.1917x over previous
#include <cuda_runtime.h>
#include <cuda_bf16.h>

#define D     64
#define DE    16
#define HDIM  128
#define DOUT  64
#define MAXN  100000
#define MAXE  1600000
#define TE    64

// Scratch (device globals — allocation-free contract)
__device__ float g_P[(size_t)MAXN * HDIM];    // X @ We1[0:64]  + be1
__device__ float g_Q[(size_t)MAXN * HDIM];    // X @ We1[64:128]
__device__ float g_agg[(size_t)MAXN * DOUT];  // segment sum

__device__ __forceinline__ float siluf(float x) {
    return __fdividef(x, 1.0f + __expf(-x));
}
__device__ __forceinline__ float sigmoidf_(float x) {
    return __fdividef(1.0f, 1.0f + __expf(-x));
}

// ---- packed f32x2 helpers (ptxas never auto-fuses these) ----
__device__ __forceinline__ unsigned long long pk2(float x, float y) {
    unsigned long long r;
    asm("mov.b64 %0, {%1, %2};" : "=l"(r) : "f"(x), "f"(y));
    return r;
}
__device__ __forceinline__ unsigned long long fma2(unsigned long long a,
                                                   unsigned long long b,
                                                   unsigned long long c) {
    unsigned long long d;
    asm("fma.rn.f32x2 %0, %1, %2, %3;" : "=l"(d) : "l"(a), "l"(b), "l"(c));
    return d;
}
__device__ __forceinline__ float2 upk2(unsigned long long v) {
    float2 f;
    asm("mov.b64 {%0, %1}, %2;" : "=f"(f.x), "=f"(f.y) : "l"(v));
    return f;
}
__device__ __forceinline__ void red_add_v4(float* p, float a, float b, float c, float d) {
    asm volatile("red.global.add.v4.f32 [%0], {%1, %2, %3, %4};"
                 :: "l"(p), "f"(a), "f"(b), "f"(c), "f"(d) : "memory");
}

// ---------------------------------------------------------------- zero agg
__global__ void zero_agg_kernel(long long n4) {
    long long i = (long long)blockIdx.x * blockDim.x + threadIdx.x;
    const long long stride = (long long)gridDim.x * blockDim.x;
    float4* p = (float4*)g_agg;
    const float4 z = make_float4(0.f, 0.f, 0.f, 0.f);
    for (; i < n4; i += stride) p[i] = z;
}

// ---------------------------------------------------- P/Q precompute (16 nodes/block)
#define PNODES 16
__global__ __launch_bounds__(128) void precompute_kernel(
    const float* __restrict__ X, const float* __restrict__ We1,
    const float* __restrict__ be1, int N)
{
    __shared__ float x_sh[D][PNODES + 2];   // transposed: x_sh[k][node]
    const int t = threadIdx.x;              // 0..127 -> hidden unit
    const int nb = blockIdx.x * PNODES;

    for (int idx = t; idx < PNODES * D; idx += 128) {
        const int m = idx >> 6, k = idx & 63;
        const int n = nb + m;
        x_sh[k][m] = (n < N) ? X[(long long)n * D + k] : 0.f;
    }
    __syncthreads();

    const float b = be1[t];
    unsigned long long accP[PNODES / 2], accQ[PNODES / 2];
#pragma unroll
    for (int mm = 0; mm < PNODES / 2; mm++) {
        accP[mm] = pk2(b, b);
        accQ[mm] = pk2(0.f, 0.f);
    }

#pragma unroll 4
    for (int k = 0; k < D; k++) {
        const float w1 = We1[k * HDIM + t];
        const float w2 = We1[(D + k) * HDIM + t];
        const unsigned long long w11 = pk2(w1, w1);
        const unsigned long long w22 = pk2(w2, w2);
#pragma unroll
        for (int mm = 0; mm < PNODES / 2; mm++) {
            const float2 xv = *(const float2*)&x_sh[k][2 * mm];
            const unsigned long long xx = pk2(xv.x, xv.y);
            accP[mm] = fma2(xx, w11, accP[mm]);
            accQ[mm] = fma2(xx, w22, accQ[mm]);
        }
    }
#pragma unroll
    for (int mm = 0; mm < PNODES / 2; mm++) {
        const float2 p = upk2(accP[mm]);
        const float2 q = upk2(accQ[mm]);
        const int n0 = nb + 2 * mm, n1 = n0 + 1;
        if (n0 < N) { g_P[(long long)n0 * HDIM + t] = p.x; g_Q[(long long)n0 * HDIM + t] = q.x; }
        if (n1 < N) { g_P[(long long)n1 * HDIM + t] = p.y; g_Q[(long long)n1 * HDIM + t] = q.y; }
    }
}

// ---------------------------------------------------------------- fused edge kernel
__global__ __launch_bounds__(256, 2) void edge_kernel(
    const float* __restrict__ X, const int* __restrict__ ei,
    const float* __restrict__ EF, const float* __restrict__ We1,
    const float* __restrict__ We2, const float* __restrict__ be2,
    const float* __restrict__ Wa, const float* __restrict__ ba,
    int N, int E)
{
    __shared__ float A_sh[TE][HDIM + 4];
    __shared__ float attn_sh[TE];
    __shared__ int   fi_sh[TE];

    const int tid  = threadIdx.x;
    const int lane = tid & 31;
    const int warp = tid >> 5;   // 0..7

    // W1c slice in registers: w1c4[k] = We1[(2D+k)*H + 4*lane .. +3]
    float4 w1c4[DE];
#pragma unroll
    for (int k = 0; k < DE; k++)
        w1c4[k] = *(const float4*)(We1 + (2 * D + k) * HDIM + 4 * lane);

    const float2 wa2 = ((const float2*)Wa)[lane];
    const float  ba0 = ba[0];

    const int numTiles = (E + TE - 1) / TE;
    for (int tile = blockIdx.x; tile < numTiles; tile += gridDim.x) {
        const int base = tile * TE;

        // -------- phase 1: warp computes layer-1 for 8 edges --------
        for (int s = 0; s < 8; s++) {
            const int eL = warp * 8 + s;
            const int e  = base + eL;
            float4 a = make_float4(0.f, 0.f, 0.f, 0.f);
            if (e < E) {
                const int iN = ei[e];
                const int jN = ei[E + e];
                const float4 pv = ((const float4*)(g_P + (long long)iN * HDIM))[lane];
                const float4 qv = ((const float4*)(g_Q + (long long)jN * HDIM))[lane];
                a.x = pv.x + qv.x; a.y = pv.y + qv.y;
                a.z = pv.z + qv.z; a.w = pv.w + qv.w;
                const float4* EF4 = (const float4*)(EF + (long long)e * DE);
#pragma unroll
                for (int j = 0; j < 4; j++) {
                    const float4 ef = __ldg(&EF4[j]);
                    const float4 w0 = w1c4[4 * j + 0];
                    const float4 w1 = w1c4[4 * j + 1];
                    const float4 w2 = w1c4[4 * j + 2];
                    const float4 w3 = w1c4[4 * j + 3];
                    a.x += ef.x * w0.x + ef.y * w1.x + ef.z * w2.x + ef.w * w3.x;
                    a.y += ef.x * w0.y + ef.y * w1.y + ef.z * w2.y + ef.w * w3.y;
                    a.z += ef.x * w0.z + ef.y * w1.z + ef.z * w2.z + ef.w * w3.z;
                    a.w += ef.x * w0.w + ef.y * w1.w + ef.z * w2.w + ef.w * w3.w;
                }
                a.x = siluf(a.x); a.y = siluf(a.y); a.z = siluf(a.z); a.w = siluf(a.w);

                // attention gate on |h_i - h_j|
                const float2 xi = ((const float2*)(X + (long long)iN * D))[lane];
                const float2 xj = ((const float2*)(X + (long long)jN * D))[lane];
                float p = fabsf(xi.x - xj.x) * wa2.x + fabsf(xi.y - xj.y) * wa2.y;
#pragma unroll
                for (int off = 16; off > 0; off >>= 1)
                    p += __shfl_down_sync(0xffffffffu, p, off);
                if (lane == 0) {
                    attn_sh[eL] = sigmoidf_(p + ba0);
                    fi_sh[eL]   = iN;
                }
            } else if (lane == 0) {
                attn_sh[eL] = 0.f;
                fi_sh[eL]   = 0;
            }
            *(float4*)&A_sh[eL][4 * lane] = a;
        }
        __syncthreads();

        // -------- phase 2: 64x64x128 GEMM with packed f32x2 FFMA --------
        const int tx = tid & 15;   // output cols 4*tx..+3
        const int ty = tid >> 4;   // edge rows  4*ty..+3
        unsigned long long acc01[4], acc23[4];
        const unsigned long long z2 = pk2(0.f, 0.f);
#pragma unroll
        for (int m = 0; m < 4; m++) { acc01[m] = z2; acc23[m] = z2; }

#pragma unroll 4
        for (int k = 0; k < HDIM; k++) {
            const float4 w = *(const float4*)(We2 + k * DOUT + 4 * tx);
            const unsigned long long w01 = pk2(w.x, w.y);
            const unsigned long long w23 = pk2(w.z, w.w);
#pragma unroll
            for (int m = 0; m < 4; m++) {
                const float a = A_sh[4 * ty + m][k];
                const unsigned long long aa = pk2(a, a);
                acc01[m] = fma2(aa, w01, acc01[m]);
                acc23[m] = fma2(aa, w23, acc23[m]);
            }
        }

        const float4 b2 = *(const float4*)(be2 + 4 * tx);
#pragma unroll
        for (int m = 0; m < 4; m++) {
            const int eL = 4 * ty + m;
            if (base + eL < E) {
                const float at = attn_sh[eL];
                const float2 r01 = upk2(acc01[m]);
                const float2 r23 = upk2(acc23[m]);
                float* aggp = g_agg + (long long)fi_sh[eL] * DOUT + 4 * tx;
                red_add_v4(aggp,
                           siluf(r01.x + b2.x) * at,
                           siluf(r01.y + b2.y) * at,
                           siluf(r23.x + b2.z) * at,
                           siluf(r23.y + b2.w) * at);
            }
        }
        __syncthreads();
    }
}

// ---------------------------------------------------------------- node MLP (64 nodes/block)
#define NT 64
__global__ __launch_bounds__(256, 2) void node_kernel(
    const float* __restrict__ X, const float* __restrict__ Wn1,
    const float* __restrict__ bn1, const float* __restrict__ Wn2,
    const float* __restrict__ bn2, float* __restrict__ out, int N)
{
    __shared__ float in_sh[NT][HDIM + 4];
    __shared__ float hid_sh[NT][HDIM + 4];
    const int tid = threadIdx.x;
    const int nb  = blockIdx.x * NT;

    // load concat [X | agg] tile
    const float4 z4 = make_float4(0.f, 0.f, 0.f, 0.f);
    for (int i = tid; i < NT * 16; i += 256) {
        const int r = i >> 4, c = i & 15;
        const int n = nb + r;
        float4 xv = z4, gv = z4;
        if (n < N) {
            xv = ((const float4*)X)[(long long)n * 16 + c];
            gv = ((const float4*)g_agg)[(long long)n * 16 + c];
        }
        *(float4*)&in_sh[r][4 * c]      = xv;
        *(float4*)&in_sh[r][D + 4 * c]  = gv;
    }
    __syncthreads();

    const int tx = tid & 15;
    const int ty = tid >> 4;
    const unsigned long long z2 = pk2(0.f, 0.f);

    // -------- GEMM1: hid = silu(in @ Wn1 + bn1), two 64-col halves --------
#pragma unroll
    for (int hh = 0; hh < 2; hh++) {
        unsigned long long acc01[4], acc23[4];
#pragma unroll
        for (int m = 0; m < 4; m++) { acc01[m] = z2; acc23[m] = z2; }

#pragma unroll 4
        for (int k = 0; k < HDIM; k++) {
            const float4 w = *(const float4*)(Wn1 + k * HDIM + hh * 64 + 4 * tx);
            const unsigned long long w01 = pk2(w.x, w.y);
            const unsigned long long w23 = pk2(w.z, w.w);
#pragma unroll
            for (int m = 0; m < 4; m++) {
                const float a = in_sh[4 * ty + m][k];
                const unsigned long long aa = pk2(a, a);
                acc01[m] = fma2(aa, w01, acc01[m]);
                acc23[m] = fma2(aa, w23, acc23[m]);
            }
        }
        const float4 b1 = *(const float4*)(bn1 + hh * 64 + 4 * tx);
#pragma unroll
        for (int m = 0; m < 4; m++) {
            const float2 r01 = upk2(acc01[m]);
            const float2 r23 = upk2(acc23[m]);
            float4 h;
            h.x = siluf(r01.x + b1.x);
            h.y = siluf(r01.y + b1.y);
            h.z = siluf(r23.x + b1.z);
            h.w = siluf(r23.y + b1.w);
            *(float4*)&hid_sh[4 * ty + m][hh * 64 + 4 * tx] = h;
        }
    }
    __syncthreads();

    // -------- GEMM2: out = hid @ Wn2 + bn2 --------
    unsigned long long acc01[4], acc23[4];
#pragma unroll
    for (int m = 0; m < 4; m++) { acc01[m] = z2; acc23[m] = z2; }

#pragma unroll 4
    for (int k = 0; k < HDIM; k++) {
        const float4 w = *(const float4*)(Wn2 + k * DOUT + 4 * tx);
        const unsigned long long w01 = pk2(w.x, w.y);
        const unsigned long long w23 = pk2(w.z, w.w);
#pragma unroll
        for (int m = 0; m < 4; m++) {
            const float a = hid_sh[4 * ty + m][k];
            const unsigned long long aa = pk2(a, a);
            acc01[m] = fma2(aa, w01, acc01[m]);
            acc23[m] = fma2(aa, w23, acc23[m]);
        }
    }
    const float4 b2 = *(const float4*)(bn2 + 4 * tx);
#pragma unroll
    for (int m = 0; m < 4; m++) {
        const int n = nb + 4 * ty + m;
        if (n < N) {
            const float2 r01 = upk2(acc01[m]);
            const float2 r23 = upk2(acc23[m]);
            float4 o;
            o.x = r01.x + b2.x; o.y = r01.y + b2.y;
            o.z = r23.x + b2.z; o.w = r23.y + b2.w;
            *(float4*)(out + (long long)n * DOUT + 4 * tx) = o;
        }
    }
}

// ---------------------------------------------------------------- tail copies
__global__ void tail_kernel(const int* __restrict__ ei,
                            const float* __restrict__ EF,
                            float* __restrict__ out,
                            long long offEI, long long nEI, long long nEF)
{
    const long long tid4 = (long long)blockIdx.x * blockDim.x + threadIdx.x;
    const long long stride = (long long)gridDim.x * blockDim.x;

    // edge_index -> float (vectorized over int4)
    const long long nEI4 = nEI >> 2;
    const int4* ei4 = (const int4*)ei;
    for (long long i = tid4; i < nEI4; i += stride) {
        const int4 v = ei4[i];
        float4 f;
        f.x = (float)v.x; f.y = (float)v.y; f.z = (float)v.z; f.w = (float)v.w;
        *(float4*)(out + offEI + 4 * i) = f;
    }
    for (long long i = nEI4 * 4 + tid4; i < nEI; i += stride)
        out[offEI + i] = (float)ei[i];

    // edge_features copy (float4)
    const long long offEF = offEI + nEI;
    const long long nEF4 = nEF >> 2;
    const float4* EF4 = (const float4*)EF;
    for (long long i = tid4; i < nEF4; i += stride)
        *(float4*)(out + offEF + 4 * i) = EF4[i];
    for (long long i = nEF4 * 4 + tid4; i < nEF; i += stride)
        out[offEF + i] = EF[i];
}

// ---------------------------------------------------------------- launch
extern "C" void kernel_launch(void* const* d_in, const int* in_sizes, int n_in,
                              void* d_out, int out_size)
{
    const float* X   = (const float*)d_in[0];
    const int*   ei  = (const int*)d_in[1];
    const float* EF  = (const float*)d_in[2];
    const float* We1 = (const float*)d_in[3];
    const float* be1 = (const float*)d_in[4];
    const float* We2 = (const float*)d_in[5];
    const float* be2 = (const float*)d_in[6];
    const float* Wa  = (const float*)d_in[7];
    const float* ba  = (const float*)d_in[8];
    const float* Wn1 = (const float*)d_in[9];
    const float* bn1 = (const float*)d_in[10];
    const float* Wn2 = (const float*)d_in[11];
    const float* bn2 = (const float*)d_in[12];

    const int N = in_sizes[0] / D;
    const int E = in_sizes[2] / DE;
    float* out = (float*)d_out;

    zero_agg_kernel<<<512, 256>>>(((long long)N * DOUT) / 4);
    precompute_kernel<<<(N + PNODES - 1) / PNODES, 128>>>(X, We1, be1, N);
    edge_kernel<<<1184, 256>>>(X, ei, EF, We1, We2, be2, Wa, ba, N, E);
    node_kernel<<<(N + NT - 1) / NT, 256>>>(X, Wn1, bn1, Wn2, bn2, out, N);

    const long long n64 = (long long)N * DOUT;
    long long avail = (long long)out_size - n64;
    if (avail > 0) {
        long long nEI = 2LL * E;
        if (nEI > avail) nEI = avail;
        long long nEF = avail - nEI;
        const long long maxEF = (long long)E * DE;
        if (nEF > maxEF) nEF = maxEF;
        tail_kernel<<<2048, 256>>>(ei, EF, out, n64, nEI, nEF);
    }
}

// round 8
// speedup vs baseline: 1.8968x; 1.5917x over previous
#include <cuda_runtime.h>
#include <cuda_bf16.h>
#include <cstdint>

#define D     64
#define DE    16
#define HDIM  128
#define DOUT  64
#define MAXN  100000
#define MAXE  1600000
#define TE    64

// Scratch (device globals — allocation-free contract)
__device__ float g_P[(size_t)MAXN * HDIM];    // X @ We1[0:64]  + be1
__device__ float g_Q[(size_t)MAXN * HDIM];    // X @ We1[64:128]
__device__ float g_agg[(size_t)MAXN * DOUT];  // segment sum

__device__ __forceinline__ float siluf(float x) {
    return __fdividef(x, 1.0f + __expf(-x));
}
__device__ __forceinline__ float sigmoidf_(float x) {
    return __fdividef(1.0f, 1.0f + __expf(-x));
}

// ---- packed f32x2 helpers ----
__device__ __forceinline__ unsigned long long pk2(float x, float y) {
    unsigned long long r;
    asm("mov.b64 %0, {%1, %2};" : "=l"(r) : "f"(x), "f"(y));
    return r;
}
__device__ __forceinline__ unsigned long long fma2(unsigned long long a,
                                                   unsigned long long b,
                                                   unsigned long long c) {
    unsigned long long d;
    asm("fma.rn.f32x2 %0, %1, %2, %3;" : "=l"(d) : "l"(a), "l"(b), "l"(c));
    return d;
}
__device__ __forceinline__ float2 upk2(unsigned long long v) {
    float2 f;
    asm("mov.b64 {%0, %1}, %2;" : "=f"(f.x), "=f"(f.y) : "l"(v));
    return f;
}
__device__ __forceinline__ void red_add_v2(float* p, float a, float b) {
    asm volatile("red.global.add.v2.f32 [%0], {%1, %2};"
                 :: "l"(p), "f"(a), "f"(b) : "memory");
}
__device__ __forceinline__ uint32_t tf32b(float x) {
    uint32_t r;
    asm("cvt.rna.tf32.f32 %0, %1;" : "=r"(r) : "f"(x));
    return r;
}
__device__ __forceinline__ void mma_tf32(float acc[4], uint32_t a0, uint32_t a1,
                                         uint32_t a2, uint32_t a3,
                                         uint32_t b0, uint32_t b1) {
    asm volatile(
        "mma.sync.aligned.m16n8k8.row.col.f32.tf32.tf32.f32 "
        "{%0,%1,%2,%3}, {%4,%5,%6,%7}, {%8,%9}, {%0,%1,%2,%3};"
        : "+f"(acc[0]), "+f"(acc[1]), "+f"(acc[2]), "+f"(acc[3])
        : "r"(a0), "r"(a1), "r"(a2), "r"(a3), "r"(b0), "r"(b1));
}

// ---------------------------------------------------------------- zero agg
__global__ void zero_agg_kernel(long long n4) {
    long long i = (long long)blockIdx.x * blockDim.x + threadIdx.x;
    const long long stride = (long long)gridDim.x * blockDim.x;
    float4* p = (float4*)g_agg;
    const float4 z = make_float4(0.f, 0.f, 0.f, 0.f);
    for (; i < n4; i += stride) p[i] = z;
}

// ---------------------------------------------------- P/Q precompute (16 nodes/block)
#define PNODES 16
__global__ __launch_bounds__(128) void precompute_kernel(
    const float* __restrict__ X, const float* __restrict__ We1,
    const float* __restrict__ be1, int N)
{
    __shared__ float x_sh[D][PNODES + 2];
    const int t = threadIdx.x;
    const int nb = blockIdx.x * PNODES;

    for (int idx = t; idx < PNODES * D; idx += 128) {
        const int m = idx >> 6, k = idx & 63;
        const int n = nb + m;
        x_sh[k][m] = (n < N) ? X[(long long)n * D + k] : 0.f;
    }
    __syncthreads();

    const float b = be1[t];
    unsigned long long accP[PNODES / 2], accQ[PNODES / 2];
#pragma unroll
    for (int mm = 0; mm < PNODES / 2; mm++) {
        accP[mm] = pk2(b, b);
        accQ[mm] = pk2(0.f, 0.f);
    }

#pragma unroll 4
    for (int k = 0; k < D; k++) {
        const float w1 = We1[k * HDIM + t];
        const float w2 = We1[(D + k) * HDIM + t];
        const unsigned long long w11 = pk2(w1, w1);
        const unsigned long long w22 = pk2(w2, w2);
#pragma unroll
        for (int mm = 0; mm < PNODES / 2; mm++) {
            const float2 xv = *(const float2*)&x_sh[k][2 * mm];
            const unsigned long long xx = pk2(xv.x, xv.y);
            accP[mm] = fma2(xx, w11, accP[mm]);
            accQ[mm] = fma2(xx, w22, accQ[mm]);
        }
    }
#pragma unroll
    for (int mm = 0; mm < PNODES / 2; mm++) {
        const float2 p = upk2(accP[mm]);
        const float2 q = upk2(accQ[mm]);
        const int n0 = nb + 2 * mm, n1 = n0 + 1;
        if (n0 < N) { g_P[(long long)n0 * HDIM + t] = p.x; g_Q[(long long)n0 * HDIM + t] = q.x; }
        if (n1 < N) { g_P[(long long)n1 * HDIM + t] = p.y; g_Q[(long long)n1 * HDIM + t] = q.y; }
    }
}

// ---------------------------------------------------------------- fused edge kernel
// Dynamic smem layout:
//   A_sh   : uint32 [TE][HDIM+4]  (tf32 activations)      33792 B
//   Wfrag  : uint2  [128][32]     (We2 mma B fragments)   32768 B
//   w1c_sh : float  [DE][HDIM]                             8192 B
//   attn_sh: float  [TE]                                    256 B
//   fi_sh  : int    [TE]                                    256 B
#define EDGE_SMEM (33792 + 32768 + 8192 + 256 + 256)

__global__ __launch_bounds__(256, 3) void edge_kernel(
    const float* __restrict__ X, const int* __restrict__ ei,
    const float* __restrict__ EF, const float* __restrict__ We1,
    const float* __restrict__ We2, const float* __restrict__ be2,
    const float* __restrict__ Wa, const float* __restrict__ ba,
    int N, int E)
{
    extern __shared__ char smraw[];
    uint32_t (*A_sh)[HDIM + 4] = (uint32_t(*)[HDIM + 4])smraw;
    uint2    (*Wfrag)[32]      = (uint2(*)[32])(smraw + 33792);
    float    (*w1c_sh)[HDIM]   = (float(*)[HDIM])(smraw + 33792 + 32768);
    float*   attn_sh           = (float*)(smraw + 33792 + 32768 + 8192);
    int*     fi_sh             = (int*)(smraw + 33792 + 32768 + 8192 + 256);

    const int tid  = threadIdx.x;
    const int lane = tid & 31;
    const int warp = tid >> 5;   // 0..7

    // ---- one-time per block: We2 -> mma B-fragment table (tf32), w1c -> smem ----
    for (int idx = tid; idx < 128 * 32; idx += 256) {
        const int kct = idx >> 5;          // ks*8 + ct
        const int ln  = idx & 31;
        const int ks  = kct >> 3;
        const int ct  = kct & 7;
        const int k0  = 8 * ks + (ln & 3);
        const int n   = 8 * ct + (ln >> 2);
        uint2 b;
        b.x = tf32b(We2[k0 * DOUT + n]);
        b.y = tf32b(We2[(k0 + 4) * DOUT + n]);
        Wfrag[kct][ln] = b;
    }
    for (int idx = tid; idx < DE * HDIM; idx += 256) {
        const int k = idx >> 7, t = idx & 127;
        w1c_sh[k][t] = We1[(2 * D + k) * HDIM + t];
    }
    __syncthreads();

    const float2 wa2 = ((const float2*)Wa)[lane];
    const float  ba0 = ba[0];

    // phase-2 constants per thread
    const int rg  = warp >> 1;          // row group 0..3 (rows 16rg..16rg+15)
    const int ctb = (warp & 1) * 4;     // col tiles ctb..ctb+3
    float2 bb[4];
#pragma unroll
    for (int ct = 0; ct < 4; ct++)
        bb[ct] = *(const float2*)(be2 + 8 * (ctb + ct) + 2 * (lane & 3));

    const int numTiles = (E + TE - 1) / TE;
    for (int tile = blockIdx.x; tile < numTiles; tile += gridDim.x) {
        const int base = tile * TE;

        // ================= phase 1: layer-1 for 8 edges per warp (2 batches of 4)
#pragma unroll
        for (int b4 = 0; b4 < 2; b4++) {
            const int s0 = warp * 8 + b4 * 4;
            int ii[4], jj[4], vld[4];
#pragma unroll
            for (int s = 0; s < 4; s++) {
                const int e  = base + s0 + s;
                const int el = (e < E) ? e : 0;
                vld[s] = (e < E);
                ii[s] = ei[el];
                jj[s] = ei[E + el];
            }
            float4 pv[4], qv[4];
#pragma unroll
            for (int s = 0; s < 4; s++) {
                pv[s] = ((const float4*)(g_P + (long long)ii[s] * HDIM))[lane];
                qv[s] = ((const float4*)(g_Q + (long long)jj[s] * HDIM))[lane];
            }
            float2 xi[4], xj[4];
#pragma unroll
            for (int s = 0; s < 4; s++) {
                xi[s] = ((const float2*)(X + (long long)ii[s] * D))[lane];
                xj[s] = ((const float2*)(X + (long long)jj[s] * D))[lane];
            }
#pragma unroll
            for (int s = 0; s < 4; s++) {
                const int e  = base + s0 + s;
                const int el = (e < E) ? e : 0;
                float4 a;
                a.x = pv[s].x + qv[s].x; a.y = pv[s].y + qv[s].y;
                a.z = pv[s].z + qv[s].z; a.w = pv[s].w + qv[s].w;
                const float4* EF4 = (const float4*)(EF + (long long)el * DE);
#pragma unroll
                for (int j = 0; j < 4; j++) {
                    const float4 ef = __ldg(&EF4[j]);
                    const float4 w0 = *(const float4*)&w1c_sh[4 * j + 0][4 * lane];
                    const float4 w1 = *(const float4*)&w1c_sh[4 * j + 1][4 * lane];
                    const float4 w2 = *(const float4*)&w1c_sh[4 * j + 2][4 * lane];
                    const float4 w3 = *(const float4*)&w1c_sh[4 * j + 3][4 * lane];
                    a.x += ef.x * w0.x + ef.y * w1.x + ef.z * w2.x + ef.w * w3.x;
                    a.y += ef.x * w0.y + ef.y * w1.y + ef.z * w2.y + ef.w * w3.y;
                    a.z += ef.x * w0.z + ef.y * w1.z + ef.z * w2.z + ef.w * w3.z;
                    a.w += ef.x * w0.w + ef.y * w1.w + ef.z * w2.w + ef.w * w3.w;
                }
                uint4 at4;
                at4.x = tf32b(siluf(a.x));
                at4.y = tf32b(siluf(a.y));
                at4.z = tf32b(siluf(a.z));
                at4.w = tf32b(siluf(a.w));
                *(uint4*)&A_sh[s0 + s][4 * lane] = at4;

                float p = fabsf(xi[s].x - xj[s].x) * wa2.x
                        + fabsf(xi[s].y - xj[s].y) * wa2.y;
#pragma unroll
                for (int off = 16; off > 0; off >>= 1)
                    p += __shfl_down_sync(0xffffffffu, p, off);
                if (lane == 0) {
                    attn_sh[s0 + s] = vld[s] ? sigmoidf_(p + ba0) : 0.f;
                    fi_sh[s0 + s]   = ii[s];
                }
            }
        }
        __syncthreads();

        // ================= phase 2: 64x64x128 via tf32 mma.sync =================
        float acc[4][4];
#pragma unroll
        for (int ct = 0; ct < 4; ct++)
#pragma unroll
            for (int u = 0; u < 4; u++) acc[ct][u] = 0.f;

        const int arow = 16 * rg + (lane >> 2);
#pragma unroll
        for (int ks = 0; ks < 16; ks++) {
            const int acol = 8 * ks + (lane & 3);
            const uint32_t a0 = A_sh[arow][acol];
            const uint32_t a1 = A_sh[arow + 8][acol];
            const uint32_t a2 = A_sh[arow][acol + 4];
            const uint32_t a3 = A_sh[arow + 8][acol + 4];
#pragma unroll
            for (int ct = 0; ct < 4; ct++) {
                const uint2 b = Wfrag[ks * 8 + ctb + ct][lane];
                mma_tf32(acc[ct], a0, a1, a2, a3, b.x, b.y);
            }
        }

        // epilogue: silu(acc + be2) * attn -> vector red scatter
#pragma unroll
        for (int half = 0; half < 2; half++) {
            const int eL = 16 * rg + (lane >> 2) + 8 * half;
            if (base + eL < E) {
                const float at = attn_sh[eL];
                float* aggp = g_agg + (long long)fi_sh[eL] * DOUT;
#pragma unroll
                for (int ct = 0; ct < 4; ct++) {
                    const int col = 8 * (ctb + ct) + 2 * (lane & 3);
                    const float v0 = siluf(acc[ct][2 * half + 0] + bb[ct].x) * at;
                    const float v1 = siluf(acc[ct][2 * half + 1] + bb[ct].y) * at;
                    red_add_v2(aggp + col, v0, v1);
                }
            }
        }
        __syncthreads();
    }
}

// ---------------------------------------------------------------- node MLP (64 nodes/block)
#define NT 64
__global__ __launch_bounds__(256, 2) void node_kernel(
    const float* __restrict__ X, const float* __restrict__ Wn1,
    const float* __restrict__ bn1, const float* __restrict__ Wn2,
    const float* __restrict__ bn2, float* __restrict__ out, int N)
{
    __shared__ float in_sh[NT][HDIM + 4];
    __shared__ float hid_sh[NT][HDIM + 4];
    const int tid = threadIdx.x;
    const int nb  = blockIdx.x * NT;

    const float4 z4 = make_float4(0.f, 0.f, 0.f, 0.f);
    for (int i = tid; i < NT * 16; i += 256) {
        const int r = i >> 4, c = i & 15;
        const int n = nb + r;
        float4 xv = z4, gv = z4;
        if (n < N) {
            xv = ((const float4*)X)[(long long)n * 16 + c];
            gv = ((const float4*)g_agg)[(long long)n * 16 + c];
        }
        *(float4*)&in_sh[r][4 * c]      = xv;
        *(float4*)&in_sh[r][D + 4 * c]  = gv;
    }
    __syncthreads();

    const int tx = tid & 15;
    const int ty = tid >> 4;
    const unsigned long long z2 = pk2(0.f, 0.f);

#pragma unroll
    for (int hh = 0; hh < 2; hh++) {
        unsigned long long acc01[4], acc23[4];
#pragma unroll
        for (int m = 0; m < 4; m++) { acc01[m] = z2; acc23[m] = z2; }

#pragma unroll 4
        for (int k = 0; k < HDIM; k++) {
            const float4 w = *(const float4*)(Wn1 + k * HDIM + hh * 64 + 4 * tx);
            const unsigned long long w01 = pk2(w.x, w.y);
            const unsigned long long w23 = pk2(w.z, w.w);
#pragma unroll
            for (int m = 0; m < 4; m++) {
                const float a = in_sh[4 * ty + m][k];
                const unsigned long long aa = pk2(a, a);
                acc01[m] = fma2(aa, w01, acc01[m]);
                acc23[m] = fma2(aa, w23, acc23[m]);
            }
        }
        const float4 b1 = *(const float4*)(bn1 + hh * 64 + 4 * tx);
#pragma unroll
        for (int m = 0; m < 4; m++) {
            const float2 r01 = upk2(acc01[m]);
            const float2 r23 = upk2(acc23[m]);
            float4 h;
            h.x = siluf(r01.x + b1.x);
            h.y = siluf(r01.y + b1.y);
            h.z = siluf(r23.x + b1.z);
            h.w = siluf(r23.y + b1.w);
            *(float4*)&hid_sh[4 * ty + m][hh * 64 + 4 * tx] = h;
        }
    }
    __syncthreads();

    unsigned long long acc01[4], acc23[4];
#pragma unroll
    for (int m = 0; m < 4; m++) { acc01[m] = z2; acc23[m] = z2; }

#pragma unroll 4
    for (int k = 0; k < HDIM; k++) {
        const float4 w = *(const float4*)(Wn2 + k * DOUT + 4 * tx);
        const unsigned long long w01 = pk2(w.x, w.y);
        const unsigned long long w23 = pk2(w.z, w.w);
#pragma unroll
        for (int m = 0; m < 4; m++) {
            const float a = hid_sh[4 * ty + m][k];
            const unsigned long long aa = pk2(a, a);
            acc01[m] = fma2(aa, w01, acc01[m]);
            acc23[m] = fma2(aa, w23, acc23[m]);
        }
    }
    const float4 b2 = *(const float4*)(bn2 + 4 * tx);
#pragma unroll
    for (int m = 0; m < 4; m++) {
        const int n = nb + 4 * ty + m;
        if (n < N) {
            const float2 r01 = upk2(acc01[m]);
            const float2 r23 = upk2(acc23[m]);
            float4 o;
            o.x = r01.x + b2.x; o.y = r01.y + b2.y;
            o.z = r23.x + b2.z; o.w = r23.y + b2.w;
            *(float4*)(out + (long long)n * DOUT + 4 * tx) = o;
        }
    }
}

// ---------------------------------------------------------------- tail copies
__global__ void tail_kernel(const int* __restrict__ ei,
                            const float* __restrict__ EF,
                            float* __restrict__ out,
                            long long offEI, long long nEI, long long nEF)
{
    const long long tid4 = (long long)blockIdx.x * blockDim.x + threadIdx.x;
    const long long stride = (long long)gridDim.x * blockDim.x;

    const long long nEI4 = nEI >> 2;
    const int4* ei4 = (const int4*)ei;
    for (long long i = tid4; i < nEI4; i += stride) {
        const int4 v = ei4[i];
        float4 f;
        f.x = (float)v.x; f.y = (float)v.y; f.z = (float)v.z; f.w = (float)v.w;
        *(float4*)(out + offEI + 4 * i) = f;
    }
    for (long long i = nEI4 * 4 + tid4; i < nEI; i += stride)
        out[offEI + i] = (float)ei[i];

    const long long offEF = offEI + nEI;
    const long long nEF4 = nEF >> 2;
    const float4* EF4 = (const float4*)EF;
    for (long long i = tid4; i < nEF4; i += stride)
        *(float4*)(out + offEF + 4 * i) = EF4[i];
    for (long long i = nEF4 * 4 + tid4; i < nEF; i += stride)
        out[offEF + i] = EF[i];
}

// ---------------------------------------------------------------- launch
extern "C" void kernel_launch(void* const* d_in, const int* in_sizes, int n_in,
                              void* d_out, int out_size)
{
    const float* X   = (const float*)d_in[0];
    const int*   ei  = (const int*)d_in[1];
    const float* EF  = (const float*)d_in[2];
    const float* We1 = (const float*)d_in[3];
    const float* be1 = (const float*)d_in[4];
    const float* We2 = (const float*)d_in[5];
    const float* be2 = (const float*)d_in[6];
    const float* Wa  = (const float*)d_in[7];
    const float* ba  = (const float*)d_in[8];
    const float* Wn1 = (const float*)d_in[9];
    const float* bn1 = (const float*)d_in[10];
    const float* Wn2 = (const float*)d_in[11];
    const float* bn2 = (const float*)d_in[12];

    const int N = in_sizes[0] / D;
    const int E = in_sizes[2] / DE;
    float* out = (float*)d_out;

    static int smem_set = 0;
    if (!smem_set) {
        cudaFuncSetAttribute(edge_kernel,
                             cudaFuncAttributeMaxDynamicSharedMemorySize, EDGE_SMEM);
        smem_set = 1;
    }

    zero_agg_kernel<<<512, 256>>>(((long long)N * DOUT) / 4);
    precompute_kernel<<<(N + PNODES - 1) / PNODES, 128>>>(X, We1, be1, N);
    edge_kernel<<<444, 256, EDGE_SMEM>>>(X, ei, EF, We1, We2, be2, Wa, ba, N, E);
    node_kernel<<<(N + NT - 1) / NT, 256>>>(X, Wn1, bn1, Wn2, bn2, out, N);

    const long long n64 = (long long)N * DOUT;
    long long avail = (long long)out_size - n64;
    if (avail > 0) {
        long long nEI = 2LL * E;
        if (nEI > avail) nEI = avail;
        long long nEF = avail - nEI;
        const long long maxEF = (long long)E * DE;
        if (nEF > maxEF) nEF = maxEF;
        tail_kernel<<<2048, 256>>>(ei, EF, out, n64, nEI, nEF);
    }
}

// round 13
// speedup vs baseline: 2.3426x; 1.2350x over previous
#include <cuda_runtime.h>
#include <cuda_bf16.h>
#include <cstdint>

#define D     64
#define DE    16
#define HDIM  128
#define DOUT  64
#define MAXN  100000
#define TE    64

// Scratch (device globals — allocation-free contract)
__device__ float g_P[(size_t)MAXN * HDIM];    // X @ We1[0:64]  + be1
__device__ float g_Q[(size_t)MAXN * HDIM];    // X @ We1[64:128]
__device__ float g_agg[(size_t)MAXN * DOUT];  // segment sum

// Weight fragment tables (tf32 mma B-operands), built once by setup_kernel
__device__ uint2 g_WfragE[16 * 8 * 32];    // We2  [128][64]
__device__ uint2 g_WfragC[2 * 16 * 32];    // W1c  [16][128] (We1 rows 128..143)
__device__ uint2 g_WfragN1[16 * 16 * 32];  // Wn1  [128][128]
__device__ uint2 g_WfragN2[16 * 8 * 32];   // Wn2  [128][64]

__device__ __forceinline__ float siluf(float x) {
    return __fdividef(x, 1.0f + __expf(-x));
}
__device__ __forceinline__ float sigmoidf_(float x) {
    return __fdividef(1.0f, 1.0f + __expf(-x));
}

// ---- helpers ----
__device__ __forceinline__ unsigned long long pk2(float x, float y) {
    unsigned long long r;
    asm("mov.b64 %0, {%1, %2};" : "=l"(r) : "f"(x), "f"(y));
    return r;
}
__device__ __forceinline__ unsigned long long fma2(unsigned long long a,
                                                   unsigned long long b,
                                                   unsigned long long c) {
    unsigned long long d;
    asm("fma.rn.f32x2 %0, %1, %2, %3;" : "=l"(d) : "l"(a), "l"(b), "l"(c));
    return d;
}
__device__ __forceinline__ float2 upk2(unsigned long long v) {
    float2 f;
    asm("mov.b64 {%0, %1}, %2;" : "=f"(f.x), "=f"(f.y) : "l"(v));
    return f;
}
__device__ __forceinline__ void red_add_v2(float* p, float a, float b) {
    asm volatile("red.global.add.v2.f32 [%0], {%1, %2};"
                 :: "l"(p), "f"(a), "f"(b) : "memory");
}
__device__ __forceinline__ uint32_t tf32b(float x) {
    uint32_t r;
    asm("cvt.rna.tf32.f32 %0, %1;" : "=r"(r) : "f"(x));
    return r;
}
__device__ __forceinline__ void mma_tf32(float acc[4], uint32_t a0, uint32_t a1,
                                         uint32_t a2, uint32_t a3,
                                         uint32_t b0, uint32_t b1) {
    asm volatile(
        "mma.sync.aligned.m16n8k8.row.col.f32.tf32.tf32.f32 "
        "{%0,%1,%2,%3}, {%4,%5,%6,%7}, {%8,%9}, {%0,%1,%2,%3};"
        : "+f"(acc[0]), "+f"(acc[1]), "+f"(acc[2]), "+f"(acc[3])
        : "r"(a0), "r"(a1), "r"(a2), "r"(a3), "r"(b0), "r"(b1));
}
#define BAR_SYNC(id)   asm volatile("bar.sync %0, 256;"   :: "r"(id) : "memory")
#define BAR_ARRIVE(id) asm volatile("bar.arrive %0, 256;" :: "r"(id) : "memory")

// ---------------------------------------------------------------- setup: fragment tables
__global__ void setup_kernel(const float* __restrict__ We1, const float* __restrict__ We2,
                             const float* __restrict__ Wn1, const float* __restrict__ Wn2)
{
    const int idx = blockIdx.x * blockDim.x + threadIdx.x;

    if (idx < 16 * 8 * 32) {  // We2 -> E table
        const int lane = idx & 31, kct = idx >> 5;
        const int ks = kct >> 3, ct = kct & 7;
        const int k0 = 8 * ks + (lane & 3), n = 8 * ct + (lane >> 2);
        g_WfragE[idx] = make_uint2(tf32b(We2[k0 * DOUT + n]),
                                   tf32b(We2[(k0 + 4) * DOUT + n]));
    }
    const int i2 = idx - 4096;
    if (i2 >= 0 && i2 < 2 * 16 * 32) {  // W1c -> C table
        const int lane = i2 & 31, kct = i2 >> 5;
        const int ks = kct >> 4, ct = kct & 15;
        const int k0 = 8 * ks + (lane & 3), n = 8 * ct + (lane >> 2);
        const float* W1c = We1 + 2 * D * HDIM;
        g_WfragC[i2] = make_uint2(tf32b(W1c[k0 * HDIM + n]),
                                  tf32b(W1c[(k0 + 4) * HDIM + n]));
    }
    const int i3 = idx - 4096 - 1024;
    if (i3 >= 0 && i3 < 16 * 16 * 32) {  // Wn1 -> N1 table
        const int lane = i3 & 31, kct = i3 >> 5;
        const int ks = kct >> 4, ct = kct & 15;
        const int k0 = 8 * ks + (lane & 3), n = 8 * ct + (lane >> 2);
        g_WfragN1[i3] = make_uint2(tf32b(Wn1[k0 * HDIM + n]),
                                   tf32b(Wn1[(k0 + 4) * HDIM + n]));
    }
    const int i4 = idx - 4096 - 1024 - 8192;
    if (i4 >= 0 && i4 < 16 * 8 * 32) {  // Wn2 -> N2 table
        const int lane = i4 & 31, kct = i4 >> 5;
        const int ks = kct >> 3, ct = kct & 7;
        const int k0 = 8 * ks + (lane & 3), n = 8 * ct + (lane >> 2);
        g_WfragN2[i4] = make_uint2(tf32b(Wn2[k0 * DOUT + n]),
                                   tf32b(Wn2[(k0 + 4) * DOUT + n]));
    }
}

// ---------------------------------------------------------------- zero agg
__global__ void zero_agg_kernel(long long n4) {
    long long i = (long long)blockIdx.x * blockDim.x + threadIdx.x;
    const long long stride = (long long)gridDim.x * blockDim.x;
    float4* p = (float4*)g_agg;
    const float4 z = make_float4(0.f, 0.f, 0.f, 0.f);
    for (; i < n4; i += stride) p[i] = z;
}

// ---------------------------------------------------- P/Q precompute (16 nodes/block)
#define PNODES 16
__global__ __launch_bounds__(128) void precompute_kernel(
    const float* __restrict__ X, const float* __restrict__ We1,
    const float* __restrict__ be1, int N)
{
    __shared__ float x_sh[D][PNODES + 2];
    const int t = threadIdx.x;
    const int nb = blockIdx.x * PNODES;

    for (int idx = t; idx < PNODES * D; idx += 128) {
        const int m = idx >> 6, k = idx & 63;
        const int n = nb + m;
        x_sh[k][m] = (n < N) ? X[(long long)n * D + k] : 0.f;
    }
    __syncthreads();

    const float b = be1[t];
    unsigned long long accP[PNODES / 2], accQ[PNODES / 2];
#pragma unroll
    for (int mm = 0; mm < PNODES / 2; mm++) {
        accP[mm] = pk2(b, b);
        accQ[mm] = pk2(0.f, 0.f);
    }

#pragma unroll 4
    for (int k = 0; k < D; k++) {
        const float w1 = We1[k * HDIM + t];
        const float w2 = We1[(D + k) * HDIM + t];
        const unsigned long long w11 = pk2(w1, w1);
        const unsigned long long w22 = pk2(w2, w2);
#pragma unroll
        for (int mm = 0; mm < PNODES / 2; mm++) {
            const float2 xv = *(const float2*)&x_sh[k][2 * mm];
            const unsigned long long xx = pk2(xv.x, xv.y);
            accP[mm] = fma2(xx, w11, accP[mm]);
            accQ[mm] = fma2(xx, w22, accQ[mm]);
        }
    }
#pragma unroll
    for (int mm = 0; mm < PNODES / 2; mm++) {
        const float2 p = upk2(accP[mm]);
        const float2 q = upk2(accQ[mm]);
        const int n0 = nb + 2 * mm, n1 = n0 + 1;
        if (n0 < N) { g_P[(long long)n0 * HDIM + t] = p.x; g_Q[(long long)n0 * HDIM + t] = q.x; }
        if (n1 < N) { g_P[(long long)n1 * HDIM + t] = p.y; g_Q[(long long)n1 * HDIM + t] = q.y; }
    }
}

// ---------------------------------------------------------------- warp-specialized edge kernel
// Ring of 2 buffers. Per buffer:
//   A    : uint32 [64][132]  (cols 0..127 data, col 128 attn, col 129 first-idx)
//   EFsh : uint32 [64][16]   (tf32 edge features)
// Producers (warps 0-3): gather P+Q (fp32 -> A), X attn, EF (tf32).
// Consumers (warps 4-7): pre-GEMM (EF@W1c + PQ), silu -> tf32 A, main GEMM, scatter.
#define ASTRIDE 132
#define ABUF_U32 (64 * ASTRIDE)
#define EBUF_U32 (64 * 16)
#define EDGE_SMEM ((2 * ABUF_U32 + 2 * EBUF_U32) * 4)   // 75776 B

__global__ __launch_bounds__(256, 3) void edge_kernel(
    const float* __restrict__ X, const int* __restrict__ ei,
    const float* __restrict__ EF, const float* __restrict__ Wa,
    const float* __restrict__ ba, const float* __restrict__ be2,
    int N, int E)
{
    extern __shared__ uint32_t sm[];
    uint32_t* Abase  = sm;                       // [2][64][132]
    uint32_t* EFbase = sm + 2 * ABUF_U32;        // [2][64][16]

    const int tid  = threadIdx.x;
    const int lane = tid & 31;
    const int warp = tid >> 5;
    const int numTiles = (E + TE - 1) / TE;

    if (warp < 4) {
        // ======================= PRODUCERS =======================
        const float2 wa2 = ((const float2*)Wa)[lane];
        const float  ba0 = ba[0];
        int it = 0;
        for (int tile = blockIdx.x; tile < numTiles; tile += gridDim.x, it++) {
            const int b = it & 1;
            uint32_t* A   = Abase  + b * ABUF_U32;
            uint32_t* EFs = EFbase + b * EBUF_U32;
            if (it >= 2) BAR_SYNC(3 + b);
            const int base = tile * TE;

#pragma unroll
            for (int b4 = 0; b4 < 4; b4++) {
                const int s0 = warp * 16 + b4 * 4;
                int ii[4], jj[4];
#pragma unroll
                for (int s = 0; s < 4; s++) {
                    int e = base + s0 + s;
                    if (e >= E) e = 0;
                    ii[s] = ei[e];
                    jj[s] = ei[E + e];
                }
                float4 pv[4], qv[4];
#pragma unroll
                for (int s = 0; s < 4; s++) {
                    pv[s] = ((const float4*)(g_P + (long long)ii[s] * HDIM))[lane];
                    qv[s] = ((const float4*)(g_Q + (long long)jj[s] * HDIM))[lane];
                }
                // EF copy (tf32), lanes 0-15: one (edge, quarter) each
                if (lane < 16) {
                    const int s = lane >> 2, part = lane & 3;
                    int e = base + s0 + s;
                    if (e >= E) e = 0;
                    const float4 f = __ldg((const float4*)(EF + (long long)e * DE) + part);
                    uint4 u;
                    u.x = tf32b(f.x); u.y = tf32b(f.y);
                    u.z = tf32b(f.z); u.w = tf32b(f.w);
                    *(uint4*)&EFs[(s0 + s) * 16 + 4 * part] = u;
                }
#pragma unroll
                for (int s = 0; s < 4; s++) {
                    const int row = s0 + s;
                    float4 a;
                    a.x = pv[s].x + qv[s].x; a.y = pv[s].y + qv[s].y;
                    a.z = pv[s].z + qv[s].z; a.w = pv[s].w + qv[s].w;
                    *(float4*)&A[row * ASTRIDE + 4 * lane] = a;   // fp32 PQ

                    const float2 xi = ((const float2*)(X + (long long)ii[s] * D))[lane];
                    const float2 xj = ((const float2*)(X + (long long)jj[s] * D))[lane];
                    float p = fabsf(xi.x - xj.x) * wa2.x + fabsf(xi.y - xj.y) * wa2.y;
#pragma unroll
                    for (int off = 16; off > 0; off >>= 1)
                        p += __shfl_down_sync(0xffffffffu, p, off);
                    if (lane == 0) {
                        const int e = base + row;
                        A[row * ASTRIDE + 128] =
                            __float_as_uint((e < E) ? sigmoidf_(p + ba0) : 0.f);
                        A[row * ASTRIDE + 129] = (uint32_t)ii[s];
                    }
                }
            }
            __threadfence_block();
            BAR_ARRIVE(1 + b);
        }
    } else {
        // ======================= CONSUMERS =======================
        const int cw = warp - 4;
        const int r0 = 16 * cw;
        float2 bb[8];
#pragma unroll
        for (int ct = 0; ct < 8; ct++)
            bb[ct] = *(const float2*)(be2 + 8 * ct + 2 * (lane & 3));

        int it = 0;
        for (int tile = blockIdx.x; tile < numTiles; tile += gridDim.x, it++) {
            const int b = it & 1;
            uint32_t* A   = Abase  + b * ABUF_U32;
            uint32_t* EFs = EFbase + b * EBUF_U32;
            BAR_SYNC(1 + b);
            const int base = tile * TE;
            const int rA = r0 + (lane >> 2);

            // ---- stage A: acc = PQ + EF@W1c, silu, back to A as tf32 ----
#pragma unroll
            for (int hf = 0; hf < 2; hf++) {
                float acc2[8][4];
#pragma unroll
                for (int ct = 0; ct < 8; ct++) {
                    const int col = 8 * (8 * hf + ct) + 2 * (lane & 3);
                    const float2 v0 = *(const float2*)&A[rA * ASTRIDE + col];
                    const float2 v1 = *(const float2*)&A[(rA + 8) * ASTRIDE + col];
                    acc2[ct][0] = v0.x; acc2[ct][1] = v0.y;
                    acc2[ct][2] = v1.x; acc2[ct][3] = v1.y;
                }
#pragma unroll
                for (int ks = 0; ks < 2; ks++) {
                    const int kc = 8 * ks + (lane & 3);
                    const uint32_t a0 = EFs[rA * 16 + kc];
                    const uint32_t a1 = EFs[(rA + 8) * 16 + kc];
                    const uint32_t a2 = EFs[rA * 16 + kc + 4];
                    const uint32_t a3 = EFs[(rA + 8) * 16 + kc + 4];
#pragma unroll
                    for (int ct = 0; ct < 8; ct++) {
                        const uint2 B = g_WfragC[(ks * 16 + 8 * hf + ct) * 32 + lane];
                        mma_tf32(acc2[ct], a0, a1, a2, a3, B.x, B.y);
                    }
                }
#pragma unroll
                for (int ct = 0; ct < 8; ct++) {
                    const int col = 8 * (8 * hf + ct) + 2 * (lane & 3);
                    uint2 u0, u1;
                    u0.x = tf32b(siluf(acc2[ct][0]));
                    u0.y = tf32b(siluf(acc2[ct][1]));
                    u1.x = tf32b(siluf(acc2[ct][2]));
                    u1.y = tf32b(siluf(acc2[ct][3]));
                    *(uint2*)&A[rA * ASTRIDE + col] = u0;
                    *(uint2*)&A[(rA + 8) * ASTRIDE + col] = u1;
                }
            }
            __syncwarp();

            // ---- main GEMM: 16 rows x 64 cols x 128 k ----
            float acc[8][4];
#pragma unroll
            for (int ct = 0; ct < 8; ct++)
#pragma unroll
                for (int u = 0; u < 4; u++) acc[ct][u] = 0.f;

#pragma unroll
            for (int ks = 0; ks < 16; ks++) {
                const int acol = 8 * ks + (lane & 3);
                const uint32_t a0 = A[rA * ASTRIDE + acol];
                const uint32_t a1 = A[(rA + 8) * ASTRIDE + acol];
                const uint32_t a2 = A[rA * ASTRIDE + acol + 4];
                const uint32_t a3 = A[(rA + 8) * ASTRIDE + acol + 4];
#pragma unroll
                for (int ct = 0; ct < 8; ct++) {
                    const uint2 B = g_WfragE[(ks * 8 + ct) * 32 + lane];
                    mma_tf32(acc[ct], a0, a1, a2, a3, B.x, B.y);
                }
            }

            // ---- epilogue: silu(acc + be2) * attn -> red scatter ----
#pragma unroll
            for (int h = 0; h < 2; h++) {
                const int eL = rA + 8 * h;
                if (base + eL < E) {
                    const float at = __uint_as_float(A[eL * ASTRIDE + 128]);
                    float* aggp = g_agg + (long long)(int)A[eL * ASTRIDE + 129] * DOUT;
#pragma unroll
                    for (int ct = 0; ct < 8; ct++) {
                        const int col = 8 * ct + 2 * (lane & 3);
                        red_add_v2(aggp + col,
                                   siluf(acc[ct][2 * h + 0] + bb[ct].x) * at,
                                   siluf(acc[ct][2 * h + 1] + bb[ct].y) * at);
                    }
                }
            }
            __threadfence_block();
            BAR_ARRIVE(3 + b);
        }
    }
}

// ---------------------------------------------------------------- node MLP: tf32 MMA
#define NT 64
__global__ __launch_bounds__(256) void node_kernel(
    const float* __restrict__ X, const float* __restrict__ bn1,
    const float* __restrict__ bn2, float* __restrict__ out, int N)
{
    __shared__ uint32_t in_sh[NT][ASTRIDE];
    __shared__ uint32_t hid_sh[NT][ASTRIDE];
    const int tid  = threadIdx.x;
    const int lane = tid & 31;
    const int warp = tid >> 5;
    const int nb   = blockIdx.x * NT;

    // load concat [X | agg] as tf32
    for (int i = tid; i < NT * 32; i += 256) {
        const int r = i >> 5, c = i & 31;
        const int n = nb + r;
        float4 v = make_float4(0.f, 0.f, 0.f, 0.f);
        if (n < N) {
            v = (c < 16) ? ((const float4*)X)[(long long)n * 16 + c]
                         : ((const float4*)g_agg)[(long long)n * 16 + (c - 16)];
        }
        uint4 u;
        u.x = tf32b(v.x); u.y = tf32b(v.y); u.z = tf32b(v.z); u.w = tf32b(v.w);
        *(uint4*)&in_sh[r][4 * c] = u;
    }
    __syncthreads();

    const int rg   = warp >> 1;
    const int half = warp & 1;
    const int r0   = 16 * rg;
    const int rA   = r0 + (lane >> 2);

    // ---- GEMM1: hid = silu(in @ Wn1 + bn1); warp does 16 rows x 64 cols ----
    float acc[8][4];
#pragma unroll
    for (int ct = 0; ct < 8; ct++)
#pragma unroll
        for (int u = 0; u < 4; u++) acc[ct][u] = 0.f;

#pragma unroll
    for (int ks = 0; ks < 16; ks++) {
        const int acol = 8 * ks + (lane & 3);
        const uint32_t a0 = in_sh[rA][acol];
        const uint32_t a1 = in_sh[rA + 8][acol];
        const uint32_t a2 = in_sh[rA][acol + 4];
        const uint32_t a3 = in_sh[rA + 8][acol + 4];
#pragma unroll
        for (int ct = 0; ct < 8; ct++) {
            const uint2 B = g_WfragN1[(ks * 16 + 8 * half + ct) * 32 + lane];
            mma_tf32(acc[ct], a0, a1, a2, a3, B.x, B.y);
        }
    }
#pragma unroll
    for (int ct = 0; ct < 8; ct++) {
        const int col = 8 * (8 * half + ct) + 2 * (lane & 3);
        const float2 b1 = *(const float2*)(bn1 + col);
        uint2 u0, u1;
        u0.x = tf32b(siluf(acc[ct][0] + b1.x));
        u0.y = tf32b(siluf(acc[ct][1] + b1.y));
        u1.x = tf32b(siluf(acc[ct][2] + b1.x));
        u1.y = tf32b(siluf(acc[ct][3] + b1.y));
        *(uint2*)&hid_sh[rA][col] = u0;
        *(uint2*)&hid_sh[rA + 8][col] = u1;
    }
    __syncthreads();

    // ---- GEMM2: out = hid @ Wn2 + bn2; warp does 16 rows x 32 cols ----
    float acc2[4][4];
#pragma unroll
    for (int ct = 0; ct < 4; ct++)
#pragma unroll
        for (int u = 0; u < 4; u++) acc2[ct][u] = 0.f;

#pragma unroll
    for (int ks = 0; ks < 16; ks++) {
        const int acol = 8 * ks + (lane & 3);
        const uint32_t a0 = hid_sh[rA][acol];
        const uint32_t a1 = hid_sh[rA + 8][acol];
        const uint32_t a2 = hid_sh[rA][acol + 4];
        const uint32_t a3 = hid_sh[rA + 8][acol + 4];
#pragma unroll
        for (int ct = 0; ct < 4; ct++) {
            const uint2 B = g_WfragN2[(ks * 8 + 4 * half + ct) * 32 + lane];
            mma_tf32(acc2[ct], a0, a1, a2, a3, B.x, B.y);
        }
    }
#pragma unroll
    for (int ct = 0; ct < 4; ct++) {
        const int col = 8 * (4 * half + ct) + 2 * (lane & 3);
        const float2 b2 = *(const float2*)(bn2 + col);
#pragma unroll
        for (int h = 0; h < 2; h++) {
            const int n = nb + rA + 8 * h;
            if (n < N) {
                float2 o;
                o.x = acc2[ct][2 * h + 0] + b2.x;
                o.y = acc2[ct][2 * h + 1] + b2.y;
                *(float2*)(out + (long long)n * DOUT + col) = o;
            }
        }
    }
}

// ---------------------------------------------------------------- tail copies
__global__ void tail_kernel(const int* __restrict__ ei,
                            const float* __restrict__ EF,
                            float* __restrict__ out,
                            long long offEI, long long nEI, long long nEF)
{
    const long long tid4 = (long long)blockIdx.x * blockDim.x + threadIdx.x;
    const long long stride = (long long)gridDim.x * blockDim.x;

    const long long nEI4 = nEI >> 2;
    const int4* ei4 = (const int4*)ei;
    for (long long i = tid4; i < nEI4; i += stride) {
        const int4 v = ei4[i];
        float4 f;
        f.x = (float)v.x; f.y = (float)v.y; f.z = (float)v.z; f.w = (float)v.w;
        *(float4*)(out + offEI + 4 * i) = f;
    }
    for (long long i = nEI4 * 4 + tid4; i < nEI; i += stride)
        out[offEI + i] = (float)ei[i];

    const long long offEF = offEI + nEI;
    const long long nEF4 = nEF >> 2;
    const float4* EF4 = (const float4*)EF;
    for (long long i = tid4; i < nEF4; i += stride)
        *(float4*)(out + offEF + 4 * i) = EF4[i];
    for (long long i = nEF4 * 4 + tid4; i < nEF; i += stride)
        out[offEF + i] = EF[i];
}

// ---------------------------------------------------------------- launch
extern "C" void kernel_launch(void* const* d_in, const int* in_sizes, int n_in,
                              void* d_out, int out_size)
{
    const float* X   = (const float*)d_in[0];
    const int*   ei  = (const int*)d_in[1];
    const float* EF  = (const float*)d_in[2];
    const float* We1 = (const float*)d_in[3];
    const float* be1 = (const float*)d_in[4];
    const float* We2 = (const float*)d_in[5];
    const float* be2 = (const float*)d_in[6];
    const float* Wa  = (const float*)d_in[7];
    const float* ba  = (const float*)d_in[8];
    const float* Wn1 = (const float*)d_in[9];
    const float* bn1 = (const float*)d_in[10];
    const float* Wn2 = (const float*)d_in[11];
    const float* bn2 = (const float*)d_in[12];

    const int N = in_sizes[0] / D;
    const int E = in_sizes[2] / DE;
    float* out = (float*)d_out;

    static int smem_set = 0;
    if (!smem_set) {
        cudaFuncSetAttribute(edge_kernel,
                             cudaFuncAttributeMaxDynamicSharedMemorySize, EDGE_SMEM);
        smem_set = 1;
    }

    setup_kernel<<<68, 256>>>(We1, We2, Wn1, Wn2);
    zero_agg_kernel<<<512, 256>>>(((long long)N * DOUT) / 4);
    precompute_kernel<<<(N + PNODES - 1) / PNODES, 128>>>(X, We1, be1, N);

    const int numTiles = (E + TE - 1) / TE;
    int grid = 444;
    if (grid > numTiles) grid = numTiles;
    edge_kernel<<<grid, 256, EDGE_SMEM>>>(X, ei, EF, Wa, ba, be2, N, E);

    node_kernel<<<(N + NT - 1) / NT, 256>>>(X, bn1, bn2, out, N);

    const long long n64 = (long long)N * DOUT;
    long long avail = (long long)out_size - n64;
    if (avail > 0) {
        long long nEI = 2LL * E;
        if (nEI > avail) nEI = avail;
        long long nEF = avail - nEI;
        const long long maxEF = (long long)E * DE;
        if (nEF > maxEF) nEF = maxEF;
        tail_kernel<<<2048, 256>>>(ei, EF, out, n64, nEI, nEF);
    }
}

// round 14
// speedup vs baseline: 2.8765x; 1.2279x over previous
#include <cuda_runtime.h>
#include <cuda_fp16.h>
#include <cuda_bf16.h>
#include <cstdint>

#define D     64
#define DE    16
#define HDIM  128
#define DOUT  64
#define MAXN  100000
#define TE    64

// Scratch (device globals — allocation-free contract)
__device__ __half g_Ph[(size_t)MAXN * HDIM];  // fp16: X @ We1[0:64] + be1
__device__ __half g_Qh[(size_t)MAXN * HDIM];  // fp16: X @ We1[64:128]
__device__ __half g_Xh[(size_t)MAXN * D];     // fp16 copy of X (attn gate)
__device__ float  g_agg[(size_t)MAXN * DOUT]; // segment sum

// Weight fragment tables (tf32 mma B-operands), built once by setup_kernel
__device__ uint2 g_WfragE[16 * 8 * 32];    // We2  [128][64]
__device__ uint2 g_WfragC[2 * 16 * 32];    // W1c  [16][128]
__device__ uint2 g_WfragN1[16 * 16 * 32];  // Wn1  [128][128]
__device__ uint2 g_WfragN2[16 * 8 * 32];   // Wn2  [128][64]

__device__ __forceinline__ float siluf(float x) {
    return __fdividef(x, 1.0f + __expf(-x));
}
__device__ __forceinline__ float sigmoidf_(float x) {
    return __fdividef(1.0f, 1.0f + __expf(-x));
}

// ---- helpers ----
__device__ __forceinline__ unsigned long long pk2(float x, float y) {
    unsigned long long r;
    asm("mov.b64 %0, {%1, %2};" : "=l"(r) : "f"(x), "f"(y));
    return r;
}
__device__ __forceinline__ unsigned long long fma2(unsigned long long a,
                                                   unsigned long long b,
                                                   unsigned long long c) {
    unsigned long long d;
    asm("fma.rn.f32x2 %0, %1, %2, %3;" : "=l"(d) : "l"(a), "l"(b), "l"(c));
    return d;
}
__device__ __forceinline__ float2 upk2(unsigned long long v) {
    float2 f;
    asm("mov.b64 {%0, %1}, %2;" : "=f"(f.x), "=f"(f.y) : "l"(v));
    return f;
}
__device__ __forceinline__ void red_add_v2(float* p, float a, float b) {
    asm volatile("red.global.add.v2.f32 [%0], {%1, %2};"
                 :: "l"(p), "f"(a), "f"(b) : "memory");
}
__device__ __forceinline__ uint32_t tf32b(float x) {
    uint32_t r;
    asm("cvt.rna.tf32.f32 %0, %1;" : "=r"(r) : "f"(x));
    return r;
}
__device__ __forceinline__ void mma_tf32(float acc[4], uint32_t a0, uint32_t a1,
                                         uint32_t a2, uint32_t a3,
                                         uint32_t b0, uint32_t b1) {
    asm volatile(
        "mma.sync.aligned.m16n8k8.row.col.f32.tf32.tf32.f32 "
        "{%0,%1,%2,%3}, {%4,%5,%6,%7}, {%8,%9}, {%0,%1,%2,%3};"
        : "+f"(acc[0]), "+f"(acc[1]), "+f"(acc[2]), "+f"(acc[3])
        : "r"(a0), "r"(a1), "r"(a2), "r"(a3), "r"(b0), "r"(b1));
}
#define BAR_SYNC(id)   asm volatile("bar.sync %0, 256;"   :: "r"(id) : "memory")
#define BAR_ARRIVE(id) asm volatile("bar.arrive %0, 256;" :: "r"(id) : "memory")

// ---------------------------------------------------------------- setup: fragment tables
__global__ void setup_kernel(const float* __restrict__ We1, const float* __restrict__ We2,
                             const float* __restrict__ Wn1, const float* __restrict__ Wn2)
{
    const int idx = blockIdx.x * blockDim.x + threadIdx.x;

    if (idx < 16 * 8 * 32) {  // We2 -> E table
        const int lane = idx & 31, kct = idx >> 5;
        const int ks = kct >> 3, ct = kct & 7;
        const int k0 = 8 * ks + (lane & 3), n = 8 * ct + (lane >> 2);
        g_WfragE[idx] = make_uint2(tf32b(We2[k0 * DOUT + n]),
                                   tf32b(We2[(k0 + 4) * DOUT + n]));
    }
    const int i2 = idx - 4096;
    if (i2 >= 0 && i2 < 2 * 16 * 32) {  // W1c -> C table
        const int lane = i2 & 31, kct = i2 >> 5;
        const int ks = kct >> 4, ct = kct & 15;
        const int k0 = 8 * ks + (lane & 3), n = 8 * ct + (lane >> 2);
        const float* W1c = We1 + 2 * D * HDIM;
        g_WfragC[i2] = make_uint2(tf32b(W1c[k0 * HDIM + n]),
                                  tf32b(W1c[(k0 + 4) * HDIM + n]));
    }
    const int i3 = idx - 4096 - 1024;
    if (i3 >= 0 && i3 < 16 * 16 * 32) {  // Wn1 -> N1 table
        const int lane = i3 & 31, kct = i3 >> 5;
        const int ks = kct >> 4, ct = kct & 15;
        const int k0 = 8 * ks + (lane & 3), n = 8 * ct + (lane >> 2);
        g_WfragN1[i3] = make_uint2(tf32b(Wn1[k0 * HDIM + n]),
                                   tf32b(Wn1[(k0 + 4) * HDIM + n]));
    }
    const int i4 = idx - 4096 - 1024 - 8192;
    if (i4 >= 0 && i4 < 16 * 8 * 32) {  // Wn2 -> N2 table
        const int lane = i4 & 31, kct = i4 >> 5;
        const int ks = kct >> 3, ct = kct & 7;
        const int k0 = 8 * ks + (lane & 3), n = 8 * ct + (lane >> 2);
        g_WfragN2[i4] = make_uint2(tf32b(Wn2[k0 * DOUT + n]),
                                   tf32b(Wn2[(k0 + 4) * DOUT + n]));
    }
}

// ---------------------------------------------------------------- zero agg
__global__ void zero_agg_kernel(long long n4) {
    long long i = (long long)blockIdx.x * blockDim.x + threadIdx.x;
    const long long stride = (long long)gridDim.x * blockDim.x;
    float4* p = (float4*)g_agg;
    const float4 z = make_float4(0.f, 0.f, 0.f, 0.f);
    for (; i < n4; i += stride) p[i] = z;
}

// ---------------------------------------------------- P/Q/Xh precompute (16 nodes/block)
#define PNODES 16
__global__ __launch_bounds__(128) void precompute_kernel(
    const float* __restrict__ X, const float* __restrict__ We1,
    const float* __restrict__ be1, int N)
{
    __shared__ float x_sh[D][PNODES + 2];
    const int t = threadIdx.x;
    const int nb = blockIdx.x * PNODES;

    for (int idx = t; idx < PNODES * D; idx += 128) {
        const int m = idx >> 6, k = idx & 63;
        const int n = nb + m;
        x_sh[k][m] = (n < N) ? X[(long long)n * D + k] : 0.f;
    }
    __syncthreads();

    // fp16 copy of X (coalesced in k)
    for (int idx = t; idx < PNODES * D; idx += 128) {
        const int m = idx >> 6, k = idx & 63;
        const int n = nb + m;
        if (n < N) g_Xh[(long long)n * D + k] = __float2half_rn(x_sh[k][m]);
    }

    const float b = be1[t];
    unsigned long long accP[PNODES / 2], accQ[PNODES / 2];
#pragma unroll
    for (int mm = 0; mm < PNODES / 2; mm++) {
        accP[mm] = pk2(b, b);
        accQ[mm] = pk2(0.f, 0.f);
    }

#pragma unroll 4
    for (int k = 0; k < D; k++) {
        const float w1 = We1[k * HDIM + t];
        const float w2 = We1[(D + k) * HDIM + t];
        const unsigned long long w11 = pk2(w1, w1);
        const unsigned long long w22 = pk2(w2, w2);
#pragma unroll
        for (int mm = 0; mm < PNODES / 2; mm++) {
            const float2 xv = *(const float2*)&x_sh[k][2 * mm];
            const unsigned long long xx = pk2(xv.x, xv.y);
            accP[mm] = fma2(xx, w11, accP[mm]);
            accQ[mm] = fma2(xx, w22, accQ[mm]);
        }
    }
#pragma unroll
    for (int mm = 0; mm < PNODES / 2; mm++) {
        const float2 p = upk2(accP[mm]);
        const float2 q = upk2(accQ[mm]);
        const int n0 = nb + 2 * mm, n1 = n0 + 1;
        if (n0 < N) {
            g_Ph[(long long)n0 * HDIM + t] = __float2half_rn(p.x);
            g_Qh[(long long)n0 * HDIM + t] = __float2half_rn(q.x);
        }
        if (n1 < N) {
            g_Ph[(long long)n1 * HDIM + t] = __float2half_rn(p.y);
            g_Qh[(long long)n1 * HDIM + t] = __float2half_rn(q.y);
        }
    }
}

// ---------------------------------------------------------------- warp-specialized edge kernel
#define ASTRIDE 132
#define ABUF_U32 (64 * ASTRIDE)
#define EBUF_U32 (64 * 16)
#define EDGE_SMEM ((2 * ABUF_U32 + 2 * EBUF_U32) * 4)   // 75776 B

__global__ __launch_bounds__(256, 3) void edge_kernel(
    const int* __restrict__ ei, const float* __restrict__ EF,
    const float* __restrict__ Wa, const float* __restrict__ ba,
    const float* __restrict__ be2, int N, int E)
{
    extern __shared__ uint32_t sm[];
    uint32_t* Abase  = sm;                       // [2][64][132]
    uint32_t* EFbase = sm + 2 * ABUF_U32;        // [2][64][16]

    const int tid  = threadIdx.x;
    const int lane = tid & 31;
    const int warp = tid >> 5;
    const int numTiles = (E + TE - 1) / TE;

    if (warp < 4) {
        // ======================= PRODUCERS =======================
        const float2 wa2 = ((const float2*)Wa)[lane];
        const float  ba0 = ba[0];
        int it = 0;
        for (int tile = blockIdx.x; tile < numTiles; tile += gridDim.x, it++) {
            const int b = it & 1;
            uint32_t* A   = Abase  + b * ABUF_U32;
            uint32_t* EFs = EFbase + b * EBUF_U32;
            if (it >= 2) BAR_SYNC(3 + b);
            const int base = tile * TE;

#pragma unroll
            for (int b8 = 0; b8 < 2; b8++) {
                const int s0 = warp * 16 + b8 * 8;
                int ii[8], jj[8];
#pragma unroll
                for (int s = 0; s < 8; s++) {
                    int e = base + s0 + s;
                    if (e >= E) e = 0;
                    ii[s] = ei[e];
                    jj[s] = ei[E + e];
                }
                // fp16 gathers: P/Q rows (uint2 = 4 halves per lane), X rows (uint = 2 halves)
                uint2 pv[8], qv[8];
                uint32_t xiv[8], xjv[8];
#pragma unroll
                for (int s = 0; s < 8; s++) {
                    pv[s] = ((const uint2*)(g_Ph + (long long)ii[s] * HDIM))[lane];
                    qv[s] = ((const uint2*)(g_Qh + (long long)jj[s] * HDIM))[lane];
                }
#pragma unroll
                for (int s = 0; s < 8; s++) {
                    xiv[s] = ((const uint32_t*)(g_Xh + (long long)ii[s] * D))[lane];
                    xjv[s] = ((const uint32_t*)(g_Xh + (long long)jj[s] * D))[lane];
                }
                // EF copy (tf32): lanes 0..31 cover 8 edges x 4 quarters
                {
                    const int s = lane >> 2, part = lane & 3;
                    int e = base + s0 + s;
                    if (e >= E) e = 0;
                    const float4 f = __ldg((const float4*)(EF + (long long)e * DE) + part);
                    uint4 u;
                    u.x = tf32b(f.x); u.y = tf32b(f.y);
                    u.z = tf32b(f.z); u.w = tf32b(f.w);
                    *(uint4*)&EFs[(s0 + s) * 16 + 4 * part] = u;
                }
#pragma unroll
                for (int s = 0; s < 8; s++) {
                    const int row = s0 + s;
                    const float2 p0 = __half22float2(*(const __half2*)&pv[s].x);
                    const float2 p1 = __half22float2(*(const __half2*)&pv[s].y);
                    const float2 q0 = __half22float2(*(const __half2*)&qv[s].x);
                    const float2 q1 = __half22float2(*(const __half2*)&qv[s].y);
                    float4 a;
                    a.x = p0.x + q0.x; a.y = p0.y + q0.y;
                    a.z = p1.x + q1.x; a.w = p1.y + q1.y;
                    *(float4*)&A[row * ASTRIDE + 4 * lane] = a;   // fp32 PQ

                    const float2 xi = __half22float2(*(const __half2*)&xiv[s]);
                    const float2 xj = __half22float2(*(const __half2*)&xjv[s]);
                    float p = fabsf(xi.x - xj.x) * wa2.x + fabsf(xi.y - xj.y) * wa2.y;
#pragma unroll
                    for (int off = 16; off > 0; off >>= 1)
                        p += __shfl_down_sync(0xffffffffu, p, off);
                    if (lane == 0) {
                        const int e = base + row;
                        A[row * ASTRIDE + 128] =
                            __float_as_uint((e < E) ? sigmoidf_(p + ba0) : 0.f);
                        A[row * ASTRIDE + 129] = (uint32_t)ii[s];
                    }
                }
            }
            __threadfence_block();
            BAR_ARRIVE(1 + b);
        }
    } else {
        // ======================= CONSUMERS =======================
        const int cw = warp - 4;
        const int r0 = 16 * cw;
        float2 bb[8];
#pragma unroll
        for (int ct = 0; ct < 8; ct++)
            bb[ct] = *(const float2*)(be2 + 8 * ct + 2 * (lane & 3));

        int it = 0;
        for (int tile = blockIdx.x; tile < numTiles; tile += gridDim.x, it++) {
            const int b = it & 1;
            uint32_t* A   = Abase  + b * ABUF_U32;
            uint32_t* EFs = EFbase + b * EBUF_U32;
            BAR_SYNC(1 + b);
            const int base = tile * TE;
            const int rA = r0 + (lane >> 2);

            // ---- stage A: acc = PQ + EF@W1c, silu, back to A as tf32 ----
#pragma unroll
            for (int hf = 0; hf < 2; hf++) {
                float acc2[8][4];
#pragma unroll
                for (int ct = 0; ct < 8; ct++) {
                    const int col = 8 * (8 * hf + ct) + 2 * (lane & 3);
                    const float2 v0 = *(const float2*)&A[rA * ASTRIDE + col];
                    const float2 v1 = *(const float2*)&A[(rA + 8) * ASTRIDE + col];
                    acc2[ct][0] = v0.x; acc2[ct][1] = v0.y;
                    acc2[ct][2] = v1.x; acc2[ct][3] = v1.y;
                }
#pragma unroll
                for (int ks = 0; ks < 2; ks++) {
                    const int kc = 8 * ks + (lane & 3);
                    const uint32_t a0 = EFs[rA * 16 + kc];
                    const uint32_t a1 = EFs[(rA + 8) * 16 + kc];
                    const uint32_t a2 = EFs[rA * 16 + kc + 4];
                    const uint32_t a3 = EFs[(rA + 8) * 16 + kc + 4];
#pragma unroll
                    for (int ct = 0; ct < 8; ct++) {
                        const uint2 B = g_WfragC[(ks * 16 + 8 * hf + ct) * 32 + lane];
                        mma_tf32(acc2[ct], a0, a1, a2, a3, B.x, B.y);
                    }
                }
#pragma unroll
                for (int ct = 0; ct < 8; ct++) {
                    const int col = 8 * (8 * hf + ct) + 2 * (lane & 3);
                    uint2 u0, u1;
                    u0.x = tf32b(siluf(acc2[ct][0]));
                    u0.y = tf32b(siluf(acc2[ct][1]));
                    u1.x = tf32b(siluf(acc2[ct][2]));
                    u1.y = tf32b(siluf(acc2[ct][3]));
                    *(uint2*)&A[rA * ASTRIDE + col] = u0;
                    *(uint2*)&A[(rA + 8) * ASTRIDE + col] = u1;
                }
            }
            __syncwarp();

            // ---- main GEMM: 16 rows x 64 cols x 128 k ----
            float acc[8][4];
#pragma unroll
            for (int ct = 0; ct < 8; ct++)
#pragma unroll
                for (int u = 0; u < 4; u++) acc[ct][u] = 0.f;

#pragma unroll
            for (int ks = 0; ks < 16; ks++) {
                const int acol = 8 * ks + (lane & 3);
                const uint32_t a0 = A[rA * ASTRIDE + acol];
                const uint32_t a1 = A[(rA + 8) * ASTRIDE + acol];
                const uint32_t a2 = A[rA * ASTRIDE + acol + 4];
                const uint32_t a3 = A[(rA + 8) * ASTRIDE + acol + 4];
#pragma unroll
                for (int ct = 0; ct < 8; ct++) {
                    const uint2 B = g_WfragE[(ks * 8 + ct) * 32 + lane];
                    mma_tf32(acc[ct], a0, a1, a2, a3, B.x, B.y);
                }
            }

            // ---- epilogue: silu(acc + be2) * attn -> red scatter ----
#pragma unroll
            for (int h = 0; h < 2; h++) {
                const int eL = rA + 8 * h;
                if (base + eL < E) {
                    const float at = __uint_as_float(A[eL * ASTRIDE + 128]);
                    float* aggp = g_agg + (long long)(int)A[eL * ASTRIDE + 129] * DOUT;
#pragma unroll
                    for (int ct = 0; ct < 8; ct++) {
                        const int col = 8 * ct + 2 * (lane & 3);
                        red_add_v2(aggp + col,
                                   siluf(acc[ct][2 * h + 0] + bb[ct].x) * at,
                                   siluf(acc[ct][2 * h + 1] + bb[ct].y) * at);
                    }
                }
            }
            __threadfence_block();
            BAR_ARRIVE(3 + b);
        }
    }
}

// ---------------------------------------------------------------- node MLP: tf32 MMA
#define NT 64
__global__ __launch_bounds__(256) void node_kernel(
    const float* __restrict__ X, const float* __restrict__ bn1,
    const float* __restrict__ bn2, float* __restrict__ out, int N)
{
    __shared__ uint32_t in_sh[NT][ASTRIDE];
    __shared__ uint32_t hid_sh[NT][ASTRIDE];
    const int tid  = threadIdx.x;
    const int lane = tid & 31;
    const int warp = tid >> 5;
    const int nb   = blockIdx.x * NT;

    for (int i = tid; i < NT * 32; i += 256) {
        const int r = i >> 5, c = i & 31;
        const int n = nb + r;
        float4 v = make_float4(0.f, 0.f, 0.f, 0.f);
        if (n < N) {
            v = (c < 16) ? ((const float4*)X)[(long long)n * 16 + c]
                         : ((const float4*)g_agg)[(long long)n * 16 + (c - 16)];
        }
        uint4 u;
        u.x = tf32b(v.x); u.y = tf32b(v.y); u.z = tf32b(v.z); u.w = tf32b(v.w);
        *(uint4*)&in_sh[r][4 * c] = u;
    }
    __syncthreads();

    const int rg   = warp >> 1;
    const int half = warp & 1;
    const int r0   = 16 * rg;
    const int rA   = r0 + (lane >> 2);

    float acc[8][4];
#pragma unroll
    for (int ct = 0; ct < 8; ct++)
#pragma unroll
        for (int u = 0; u < 4; u++) acc[ct][u] = 0.f;

#pragma unroll
    for (int ks = 0; ks < 16; ks++) {
        const int acol = 8 * ks + (lane & 3);
        const uint32_t a0 = in_sh[rA][acol];
        const uint32_t a1 = in_sh[rA + 8][acol];
        const uint32_t a2 = in_sh[rA][acol + 4];
        const uint32_t a3 = in_sh[rA + 8][acol + 4];
#pragma unroll
        for (int ct = 0; ct < 8; ct++) {
            const uint2 B = g_WfragN1[(ks * 16 + 8 * half + ct) * 32 + lane];
            mma_tf32(acc[ct], a0, a1, a2, a3, B.x, B.y);
        }
    }
#pragma unroll
    for (int ct = 0; ct < 8; ct++) {
        const int col = 8 * (8 * half + ct) + 2 * (lane & 3);
        const float2 b1 = *(const float2*)(bn1 + col);
        uint2 u0, u1;
        u0.x = tf32b(siluf(acc[ct][0] + b1.x));
        u0.y = tf32b(siluf(acc[ct][1] + b1.y));
        u1.x = tf32b(siluf(acc[ct][2] + b1.x));
        u1.y = tf32b(siluf(acc[ct][3] + b1.y));
        *(uint2*)&hid_sh[rA][col] = u0;
        *(uint2*)&hid_sh[rA + 8][col] = u1;
    }
    __syncthreads();

    float acc2[4][4];
#pragma unroll
    for (int ct = 0; ct < 4; ct++)
#pragma unroll
        for (int u = 0; u < 4; u++) acc2[ct][u] = 0.f;

#pragma unroll
    for (int ks = 0; ks < 16; ks++) {
        const int acol = 8 * ks + (lane & 3);
        const uint32_t a0 = hid_sh[rA][acol];
        const uint32_t a1 = hid_sh[rA + 8][acol];
        const uint32_t a2 = hid_sh[rA][acol + 4];
        const uint32_t a3 = hid_sh[rA + 8][acol + 4];
#pragma unroll
        for (int ct = 0; ct < 4; ct++) {
            const uint2 B = g_WfragN2[(ks * 8 + 4 * half + ct) * 32 + lane];
            mma_tf32(acc2[ct], a0, a1, a2, a3, B.x, B.y);
        }
    }
#pragma unroll
    for (int ct = 0; ct < 4; ct++) {
        const int col = 8 * (4 * half + ct) + 2 * (lane & 3);
        const float2 b2 = *(const float2*)(bn2 + col);
#pragma unroll
        for (int h = 0; h < 2; h++) {
            const int n = nb + rA + 8 * h;
            if (n < N) {
                float2 o;
                o.x = acc2[ct][2 * h + 0] + b2.x;
                o.y = acc2[ct][2 * h + 1] + b2.y;
                *(float2*)(out + (long long)n * DOUT + col) = o;
            }
        }
    }
}

// ---------------------------------------------------------------- tail copies
__global__ void tail_kernel(const int* __restrict__ ei,
                            const float* __restrict__ EF,
                            float* __restrict__ out,
                            long long offEI, long long nEI, long long nEF)
{
    const long long tid4 = (long long)blockIdx.x * blockDim.x + threadIdx.x;
    const long long stride = (long long)gridDim.x * blockDim.x;

    const long long nEI4 = nEI >> 2;
    const int4* ei4 = (const int4*)ei;
    for (long long i = tid4; i < nEI4; i += stride) {
        const int4 v = ei4[i];
        float4 f;
        f.x = (float)v.x; f.y = (float)v.y; f.z = (float)v.z; f.w = (float)v.w;
        *(float4*)(out + offEI + 4 * i) = f;
    }
    for (long long i = nEI4 * 4 + tid4; i < nEI; i += stride)
        out[offEI + i] = (float)ei[i];

    const long long offEF = offEI + nEI;
    const long long nEF4 = nEF >> 2;
    const float4* EF4 = (const float4*)EF;
    for (long long i = tid4; i < nEF4; i += stride)
        *(float4*)(out + offEF + 4 * i) = EF4[i];
    for (long long i = nEF4 * 4 + tid4; i < nEF; i += stride)
        out[offEF + i] = EF[i];
}

// ---------------------------------------------------------------- launch
extern "C" void kernel_launch(void* const* d_in, const int* in_sizes, int n_in,
                              void* d_out, int out_size)
{
    const float* X   = (const float*)d_in[0];
    const int*   ei  = (const int*)d_in[1];
    const float* EF  = (const float*)d_in[2];
    const float* We1 = (const float*)d_in[3];
    const float* be1 = (const float*)d_in[4];
    const float* We2 = (const float*)d_in[5];
    const float* be2 = (const float*)d_in[6];
    const float* Wa  = (const float*)d_in[7];
    const float* ba  = (const float*)d_in[8];
    const float* Wn1 = (const float*)d_in[9];
    const float* bn1 = (const float*)d_in[10];
    const float* Wn2 = (const float*)d_in[11];
    const float* bn2 = (const float*)d_in[12];

    const int N = in_sizes[0] / D;
    const int E = in_sizes[2] / DE;
    float* out = (float*)d_out;

    static int smem_set = 0;
    if (!smem_set) {
        cudaFuncSetAttribute(edge_kernel,
                             cudaFuncAttributeMaxDynamicSharedMemorySize, EDGE_SMEM);
        smem_set = 1;
    }

    setup_kernel<<<68, 256>>>(We1, We2, Wn1, Wn2);
    zero_agg_kernel<<<512, 256>>>(((long long)N * DOUT) / 4);
    precompute_kernel<<<(N + PNODES - 1) / PNODES, 128>>>(X, We1, be1, N);

    const int numTiles = (E + TE - 1) / TE;
    int grid = 444;
    if (grid > numTiles) grid = numTiles;
    edge_kernel<<<grid, 256, EDGE_SMEM>>>(ei, EF, Wa, ba, be2, N, E);

    node_kernel<<<(N + NT - 1) / NT, 256>>>(X, bn1, bn2, out, N);

    const long long n64 = (long long)N * DOUT;
    long long avail = (long long)out_size - n64;
    if (avail > 0) {
        long long nEI = 2LL * E;
        if (nEI > avail) nEI = avail;
        long long nEF = avail - nEI;
        const long long maxEF = (long long)E * DE;
        if (nEF > maxEF) nEF = maxEF;
        tail_kernel<<<2048, 256>>>(ei, EF, out, n64, nEI, nEF);
    }
}

// round 15
// speedup vs baseline: 3.7366x; 1.2990x over previous
#include <cuda_runtime.h>
#include <cuda_fp16.h>
#include <cuda_bf16.h>
#include <cstdint>

#define D     64
#define DE    16
#define HDIM  128
#define DOUT  64
#define MAXN  100000
#define TE    64

// Scratch (device globals — allocation-free contract)
__device__ __half g_Ph[(size_t)MAXN * HDIM];  // fp16: X @ We1[0:64] + be1
__device__ __half g_Qh[(size_t)MAXN * HDIM];  // fp16: X @ We1[64:128]
__device__ __half g_Xh[(size_t)MAXN * D];     // fp16 copy of X (attn gate)
__device__ float  g_agg[(size_t)MAXN * DOUT]; // segment sum

// Weight fragment tables, built once by setup_kernel
__device__ uint2 g_WfragEh[8 * 8 * 32];    // We2  [128][64]  fp16 m16n8k16 B-frags
__device__ uint2 g_WfragCh[16 * 32];       // W1c  [16][128]  fp16 m16n8k16 B-frags
__device__ uint2 g_WfragN1[16 * 16 * 32];  // Wn1  [128][128] tf32
__device__ uint2 g_WfragN2[16 * 8 * 32];   // Wn2  [128][64]  tf32

__device__ __forceinline__ float siluf(float x) {
    return __fdividef(x, 1.0f + __expf(-x));
}
__device__ __forceinline__ float sigmoidf_(float x) {
    return __fdividef(1.0f, 1.0f + __expf(-x));
}

// ---- helpers ----
__device__ __forceinline__ unsigned long long pk2(float x, float y) {
    unsigned long long r;
    asm("mov.b64 %0, {%1, %2};" : "=l"(r) : "f"(x), "f"(y));
    return r;
}
__device__ __forceinline__ unsigned long long fma2(unsigned long long a,
                                                   unsigned long long b,
                                                   unsigned long long c) {
    unsigned long long d;
    asm("fma.rn.f32x2 %0, %1, %2, %3;" : "=l"(d) : "l"(a), "l"(b), "l"(c));
    return d;
}
__device__ __forceinline__ float2 upk2(unsigned long long v) {
    float2 f;
    asm("mov.b64 {%0, %1}, %2;" : "=f"(f.x), "=f"(f.y) : "l"(v));
    return f;
}
__device__ __forceinline__ void red_add_v2(float* p, float a, float b) {
    asm volatile("red.global.add.v2.f32 [%0], {%1, %2};"
                 :: "l"(p), "f"(a), "f"(b) : "memory");
}
__device__ __forceinline__ uint32_t tf32b(float x) {
    uint32_t r;
    asm("cvt.rna.tf32.f32 %0, %1;" : "=r"(r) : "f"(x));
    return r;
}
__device__ __forceinline__ uint32_t h2u(float lo, float hi) {
    __half2 h = __floats2half2_rn(lo, hi);
    return *(uint32_t*)&h;
}
__device__ __forceinline__ void mma_tf32(float acc[4], uint32_t a0, uint32_t a1,
                                         uint32_t a2, uint32_t a3,
                                         uint32_t b0, uint32_t b1) {
    asm volatile(
        "mma.sync.aligned.m16n8k8.row.col.f32.tf32.tf32.f32 "
        "{%0,%1,%2,%3}, {%4,%5,%6,%7}, {%8,%9}, {%0,%1,%2,%3};"
        : "+f"(acc[0]), "+f"(acc[1]), "+f"(acc[2]), "+f"(acc[3])
        : "r"(a0), "r"(a1), "r"(a2), "r"(a3), "r"(b0), "r"(b1));
}
__device__ __forceinline__ void mma_f16(float acc[4], uint32_t a0, uint32_t a1,
                                        uint32_t a2, uint32_t a3,
                                        uint32_t b0, uint32_t b1) {
    asm volatile(
        "mma.sync.aligned.m16n8k16.row.col.f32.f16.f16.f32 "
        "{%0,%1,%2,%3}, {%4,%5,%6,%7}, {%8,%9}, {%0,%1,%2,%3};"
        : "+f"(acc[0]), "+f"(acc[1]), "+f"(acc[2]), "+f"(acc[3])
        : "r"(a0), "r"(a1), "r"(a2), "r"(a3), "r"(b0), "r"(b1));
}
#define BAR_SYNC(id)   asm volatile("bar.sync %0, 256;"   :: "r"(id) : "memory")
#define BAR_ARRIVE(id) asm volatile("bar.arrive %0, 256;" :: "r"(id) : "memory")

// ---------------------------------------------------------------- setup: fragment tables
__global__ void setup_kernel(const float* __restrict__ We1, const float* __restrict__ We2,
                             const float* __restrict__ Wn1, const float* __restrict__ Wn2)
{
    const int idx = blockIdx.x * blockDim.x + threadIdx.x;

    if (idx < 8 * 8 * 32) {  // We2 -> fp16 E table (m16n8k16 B, col-major)
        const int lane = idx & 31, rest = idx >> 5;
        const int ks = rest >> 3, ct = rest & 7;
        const int n = 8 * ct + (lane >> 2);
        const int k0 = 16 * ks + 2 * (lane & 3);
        uint2 b;
        b.x = h2u(We2[k0 * DOUT + n],       We2[(k0 + 1) * DOUT + n]);
        b.y = h2u(We2[(k0 + 8) * DOUT + n], We2[(k0 + 9) * DOUT + n]);
        g_WfragEh[idx] = b;
    }
    const int i2 = idx - 2048;
    if (i2 >= 0 && i2 < 16 * 32) {  // W1c -> fp16 C table (single k16 step)
        const int lane = i2 & 31, ct = i2 >> 5;
        const int n = 8 * ct + (lane >> 2);
        const int k0 = 2 * (lane & 3);
        const float* W1c = We1 + 2 * D * HDIM;
        uint2 b;
        b.x = h2u(W1c[k0 * HDIM + n],       W1c[(k0 + 1) * HDIM + n]);
        b.y = h2u(W1c[(k0 + 8) * HDIM + n], W1c[(k0 + 9) * HDIM + n]);
        g_WfragCh[i2] = b;
    }
    const int i3 = idx - 2048 - 512;
    if (i3 >= 0 && i3 < 16 * 16 * 32) {  // Wn1 -> N1 table (tf32)
        const int lane = i3 & 31, kct = i3 >> 5;
        const int ks = kct >> 4, ct = kct & 15;
        const int k0 = 8 * ks + (lane & 3), n = 8 * ct + (lane >> 2);
        g_WfragN1[i3] = make_uint2(tf32b(Wn1[k0 * HDIM + n]),
                                   tf32b(Wn1[(k0 + 4) * HDIM + n]));
    }
    const int i4 = idx - 2048 - 512 - 8192;
    if (i4 >= 0 && i4 < 16 * 8 * 32) {  // Wn2 -> N2 table (tf32)
        const int lane = i4 & 31, kct = i4 >> 5;
        const int ks = kct >> 3, ct = kct & 7;
        const int k0 = 8 * ks + (lane & 3), n = 8 * ct + (lane >> 2);
        g_WfragN2[i4] = make_uint2(tf32b(Wn2[k0 * DOUT + n]),
                                   tf32b(Wn2[(k0 + 4) * DOUT + n]));
    }
}

// ---------------------------------------------------------------- zero agg
__global__ void zero_agg_kernel(long long n4) {
    long long i = (long long)blockIdx.x * blockDim.x + threadIdx.x;
    const long long stride = (long long)gridDim.x * blockDim.x;
    float4* p = (float4*)g_agg;
    const float4 z = make_float4(0.f, 0.f, 0.f, 0.f);
    for (; i < n4; i += stride) p[i] = z;
}

// ---------------------------------------------------- P/Q/Xh precompute (16 nodes/block)
#define PNODES 16
__global__ __launch_bounds__(128) void precompute_kernel(
    const float* __restrict__ X, const float* __restrict__ We1,
    const float* __restrict__ be1, int N)
{
    __shared__ float x_sh[D][PNODES + 2];
    const int t = threadIdx.x;
    const int nb = blockIdx.x * PNODES;

    for (int idx = t; idx < PNODES * D; idx += 128) {
        const int m = idx >> 6, k = idx & 63;
        const int n = nb + m;
        x_sh[k][m] = (n < N) ? X[(long long)n * D + k] : 0.f;
    }
    __syncthreads();

    for (int idx = t; idx < PNODES * D; idx += 128) {
        const int m = idx >> 6, k = idx & 63;
        const int n = nb + m;
        if (n < N) g_Xh[(long long)n * D + k] = __float2half_rn(x_sh[k][m]);
    }

    const float b = be1[t];
    unsigned long long accP[PNODES / 2], accQ[PNODES / 2];
#pragma unroll
    for (int mm = 0; mm < PNODES / 2; mm++) {
        accP[mm] = pk2(b, b);
        accQ[mm] = pk2(0.f, 0.f);
    }

#pragma unroll 4
    for (int k = 0; k < D; k++) {
        const float w1 = We1[k * HDIM + t];
        const float w2 = We1[(D + k) * HDIM + t];
        const unsigned long long w11 = pk2(w1, w1);
        const unsigned long long w22 = pk2(w2, w2);
#pragma unroll
        for (int mm = 0; mm < PNODES / 2; mm++) {
            const float2 xv = *(const float2*)&x_sh[k][2 * mm];
            const unsigned long long xx = pk2(xv.x, xv.y);
            accP[mm] = fma2(xx, w11, accP[mm]);
            accQ[mm] = fma2(xx, w22, accQ[mm]);
        }
    }
#pragma unroll
    for (int mm = 0; mm < PNODES / 2; mm++) {
        const float2 p = upk2(accP[mm]);
        const float2 q = upk2(accQ[mm]);
        const int n0 = nb + 2 * mm, n1 = n0 + 1;
        if (n0 < N) {
            g_Ph[(long long)n0 * HDIM + t] = __float2half_rn(p.x);
            g_Qh[(long long)n0 * HDIM + t] = __float2half_rn(q.x);
        }
        if (n1 < N) {
            g_Ph[(long long)n1 * HDIM + t] = __float2half_rn(p.y);
            g_Qh[(long long)n1 * HDIM + t] = __float2half_rn(q.y);
        }
    }
}

// ---------------------------------------------------------------- warp-specialized edge kernel
// A buffer rows are fp16 (half2 per uint32): 64 rows x 64 uint32 (+4 pad)
#define ASH 68
#define ABUF_U32 (64 * ASH)                 // 4352
#define EBUF_U32 (64 * 8)                   // 512
#define OFF_EF   (2 * ABUF_U32)             // 8704
#define OFF_ATTN (OFF_EF + 2 * EBUF_U32)    // 9728
#define OFF_FI   (OFF_ATTN + 2 * 64)        // 9856
#define EDGE_SMEM ((OFF_FI + 2 * 64) * 4)   // 39936 B

__global__ __launch_bounds__(256, 3) void edge_kernel(
    const int* __restrict__ ei, const float* __restrict__ EF,
    const float* __restrict__ Wa, const float* __restrict__ ba,
    const float* __restrict__ be2, int N, int E)
{
    extern __shared__ uint32_t sm[];

    const int tid  = threadIdx.x;
    const int lane = tid & 31;
    const int warp = tid >> 5;
    const int numTiles = (E + TE - 1) / TE;

    if (warp < 4) {
        // ======================= PRODUCERS =======================
        const float2 wa2 = ((const float2*)Wa)[lane];
        const float  ba0 = ba[0];
        int it = 0;
        for (int tile = blockIdx.x; tile < numTiles; tile += gridDim.x, it++) {
            const int b = it & 1;
            uint32_t* A    = sm + b * ABUF_U32;
            uint32_t* EFs  = sm + OFF_EF + b * EBUF_U32;
            uint32_t* attn = sm + OFF_ATTN + b * 64;
            uint32_t* fi   = sm + OFF_FI + b * 64;
            if (it >= 2) BAR_SYNC(3 + b);
            const int base = tile * TE;

#pragma unroll
            for (int b8 = 0; b8 < 2; b8++) {
                const int s0 = warp * 16 + b8 * 8;
                int ii[8], jj[8];
#pragma unroll
                for (int s = 0; s < 8; s++) {
                    int e = base + s0 + s;
                    if (e >= E) e = 0;
                    ii[s] = ei[e];
                    jj[s] = ei[E + e];
                }
                uint2 pv[8], qv[8];
                uint32_t xiv[8], xjv[8];
#pragma unroll
                for (int s = 0; s < 8; s++) {
                    pv[s] = ((const uint2*)(g_Ph + (long long)ii[s] * HDIM))[lane];
                    qv[s] = ((const uint2*)(g_Qh + (long long)jj[s] * HDIM))[lane];
                }
#pragma unroll
                for (int s = 0; s < 8; s++) {
                    xiv[s] = ((const uint32_t*)(g_Xh + (long long)ii[s] * D))[lane];
                    xjv[s] = ((const uint32_t*)(g_Xh + (long long)jj[s] * D))[lane];
                }
                // EF copy as half2: 4 lanes per edge, 2 uint32 each
                {
                    const int s = lane >> 2, part = lane & 3;
                    int e = base + s0 + s;
                    if (e >= E) e = 0;
                    const float4 f = __ldg((const float4*)(EF + (long long)e * DE) + part);
                    uint2 u;
                    u.x = h2u(f.x, f.y);
                    u.y = h2u(f.z, f.w);
                    *(uint2*)&EFs[(s0 + s) * 8 + 2 * part] = u;
                }
#pragma unroll
                for (int s = 0; s < 8; s++) {
                    const int row = s0 + s;
                    // P+Q in half2 (HADD2), store 4 halves
                    uint2 a;
                    __half2 a01 = __hadd2(*(const __half2*)&pv[s].x, *(const __half2*)&qv[s].x);
                    __half2 a23 = __hadd2(*(const __half2*)&pv[s].y, *(const __half2*)&qv[s].y);
                    a.x = *(uint32_t*)&a01;
                    a.y = *(uint32_t*)&a23;
                    *(uint2*)&A[row * ASH + 2 * lane] = a;

                    const float2 xi = __half22float2(*(const __half2*)&xiv[s]);
                    const float2 xj = __half22float2(*(const __half2*)&xjv[s]);
                    float p = fabsf(xi.x - xj.x) * wa2.x + fabsf(xi.y - xj.y) * wa2.y;
#pragma unroll
                    for (int off = 16; off > 0; off >>= 1)
                        p += __shfl_down_sync(0xffffffffu, p, off);
                    if (lane == 0) {
                        const int e = base + row;
                        attn[row] = __float_as_uint((e < E) ? sigmoidf_(p + ba0) : 0.f);
                        fi[row]   = (uint32_t)ii[s];
                    }
                }
            }
            __threadfence_block();
            BAR_ARRIVE(1 + b);
        }
    } else {
        // ======================= CONSUMERS =======================
        const int cw = warp - 4;
        const int r0 = 16 * cw;
        float2 bb[8];
#pragma unroll
        for (int ct = 0; ct < 8; ct++)
            bb[ct] = *(const float2*)(be2 + 8 * ct + 2 * (lane & 3));

        int it = 0;
        for (int tile = blockIdx.x; tile < numTiles; tile += gridDim.x, it++) {
            const int b = it & 1;
            uint32_t* A    = sm + b * ABUF_U32;
            uint32_t* EFs  = sm + OFF_EF + b * EBUF_U32;
            uint32_t* attn = sm + OFF_ATTN + b * 64;
            uint32_t* fi   = sm + OFF_FI + b * 64;
            BAR_SYNC(1 + b);
            const int base = tile * TE;
            const int rA = r0 + (lane >> 2);

            // EF A-fragment (one k16 step), reused across both halves
            const uint32_t ea0 = EFs[rA * 8 + (lane & 3)];
            const uint32_t ea1 = EFs[(rA + 8) * 8 + (lane & 3)];
            const uint32_t ea2 = EFs[rA * 8 + (lane & 3) + 4];
            const uint32_t ea3 = EFs[(rA + 8) * 8 + (lane & 3) + 4];

            // ---- stage A: acc = PQ + EF@W1c, silu, back to A as fp16 ----
#pragma unroll
            for (int hf = 0; hf < 2; hf++) {
                float acc2[8][4];
#pragma unroll
                for (int ct = 0; ct < 8; ct++) {
                    const int ui = 4 * (8 * hf + ct) + (lane & 3);
                    const float2 v0 = __half22float2(*(const __half2*)&A[rA * ASH + ui]);
                    const float2 v1 = __half22float2(*(const __half2*)&A[(rA + 8) * ASH + ui]);
                    acc2[ct][0] = v0.x; acc2[ct][1] = v0.y;
                    acc2[ct][2] = v1.x; acc2[ct][3] = v1.y;
                }
#pragma unroll
                for (int ct = 0; ct < 8; ct++) {
                    const uint2 B = g_WfragCh[(8 * hf + ct) * 32 + lane];
                    mma_f16(acc2[ct], ea0, ea1, ea2, ea3, B.x, B.y);
                }
#pragma unroll
                for (int ct = 0; ct < 8; ct++) {
                    const int ui = 4 * (8 * hf + ct) + (lane & 3);
                    A[rA * ASH + ui]       = h2u(siluf(acc2[ct][0]), siluf(acc2[ct][1]));
                    A[(rA + 8) * ASH + ui] = h2u(siluf(acc2[ct][2]), siluf(acc2[ct][3]));
                }
            }
            __syncwarp();

            // ---- main GEMM: 16 rows x 64 cols x 128 k (fp16, 8 k-steps) ----
            float acc[8][4];
#pragma unroll
            for (int ct = 0; ct < 8; ct++)
#pragma unroll
                for (int u = 0; u < 4; u++) acc[ct][u] = 0.f;

#pragma unroll
            for (int ks = 0; ks < 8; ks++) {
                const int kc = 8 * ks + (lane & 3);
                const uint32_t a0 = A[rA * ASH + kc];
                const uint32_t a1 = A[(rA + 8) * ASH + kc];
                const uint32_t a2 = A[rA * ASH + kc + 4];
                const uint32_t a3 = A[(rA + 8) * ASH + kc + 4];
#pragma unroll
                for (int ct = 0; ct < 8; ct++) {
                    const uint2 B = g_WfragEh[(ks * 8 + ct) * 32 + lane];
                    mma_f16(acc[ct], a0, a1, a2, a3, B.x, B.y);
                }
            }

            // ---- epilogue: silu(acc + be2) * attn -> red scatter ----
#pragma unroll
            for (int h = 0; h < 2; h++) {
                const int eL = rA + 8 * h;
                if (base + eL < E) {
                    const float at = __uint_as_float(attn[eL]);
                    float* aggp = g_agg + (long long)(int)fi[eL] * DOUT;
#pragma unroll
                    for (int ct = 0; ct < 8; ct++) {
                        const int col = 8 * ct + 2 * (lane & 3);
                        red_add_v2(aggp + col,
                                   siluf(acc[ct][2 * h + 0] + bb[ct].x) * at,
                                   siluf(acc[ct][2 * h + 1] + bb[ct].y) * at);
                    }
                }
            }
            __threadfence_block();
            BAR_ARRIVE(3 + b);
        }
    }
}

// ---------------------------------------------------------------- node MLP: tf32 MMA
#define NT 64
#define NSTRIDE 132
__global__ __launch_bounds__(256) void node_kernel(
    const float* __restrict__ X, const float* __restrict__ bn1,
    const float* __restrict__ bn2, float* __restrict__ out, int N)
{
    __shared__ uint32_t in_sh[NT][NSTRIDE];
    __shared__ uint32_t hid_sh[NT][NSTRIDE];
    const int tid  = threadIdx.x;
    const int lane = tid & 31;
    const int warp = tid >> 5;
    const int nb   = blockIdx.x * NT;

    for (int i = tid; i < NT * 32; i += 256) {
        const int r = i >> 5, c = i & 31;
        const int n = nb + r;
        float4 v = make_float4(0.f, 0.f, 0.f, 0.f);
        if (n < N) {
            v = (c < 16) ? ((const float4*)X)[(long long)n * 16 + c]
                         : ((const float4*)g_agg)[(long long)n * 16 + (c - 16)];
        }
        uint4 u;
        u.x = tf32b(v.x); u.y = tf32b(v.y); u.z = tf32b(v.z); u.w = tf32b(v.w);
        *(uint4*)&in_sh[r][4 * c] = u;
    }
    __syncthreads();

    const int rg   = warp >> 1;
    const int half = warp & 1;
    const int r0   = 16 * rg;
    const int rA   = r0 + (lane >> 2);

    float acc[8][4];
#pragma unroll
    for (int ct = 0; ct < 8; ct++)
#pragma unroll
        for (int u = 0; u < 4; u++) acc[ct][u] = 0.f;

#pragma unroll
    for (int ks = 0; ks < 16; ks++) {
        const int acol = 8 * ks + (lane & 3);
        const uint32_t a0 = in_sh[rA][acol];
        const uint32_t a1 = in_sh[rA + 8][acol];
        const uint32_t a2 = in_sh[rA][acol + 4];
        const uint32_t a3 = in_sh[rA + 8][acol + 4];
#pragma unroll
        for (int ct = 0; ct < 8; ct++) {
            const uint2 B = g_WfragN1[(ks * 16 + 8 * half + ct) * 32 + lane];
            mma_tf32(acc[ct], a0, a1, a2, a3, B.x, B.y);
        }
    }
#pragma unroll
    for (int ct = 0; ct < 8; ct++) {
        const int col = 8 * (8 * half + ct) + 2 * (lane & 3);
        const float2 b1 = *(const float2*)(bn1 + col);
        uint2 u0, u1;
        u0.x = tf32b(siluf(acc[ct][0] + b1.x));
        u0.y = tf32b(siluf(acc[ct][1] + b1.y));
        u1.x = tf32b(siluf(acc[ct][2] + b1.x));
        u1.y = tf32b(siluf(acc[ct][3] + b1.y));
        *(uint2*)&hid_sh[rA][col] = u0;
        *(uint2*)&hid_sh[rA + 8][col] = u1;
    }
    __syncthreads();

    float acc2[4][4];
#pragma unroll
    for (int ct = 0; ct < 4; ct++)
#pragma unroll
        for (int u = 0; u < 4; u++) acc2[ct][u] = 0.f;

#pragma unroll
    for (int ks = 0; ks < 16; ks++) {
        const int acol = 8 * ks + (lane & 3);
        const uint32_t a0 = hid_sh[rA][acol];
        const uint32_t a1 = hid_sh[rA + 8][acol];
        const uint32_t a2 = hid_sh[rA][acol + 4];
        const uint32_t a3 = hid_sh[rA + 8][acol + 4];
#pragma unroll
        for (int ct = 0; ct < 4; ct++) {
            const uint2 B = g_WfragN2[(ks * 8 + 4 * half + ct) * 32 + lane];
            mma_tf32(acc2[ct], a0, a1, a2, a3, B.x, B.y);
        }
    }
#pragma unroll
    for (int ct = 0; ct < 4; ct++) {
        const int col = 8 * (4 * half + ct) + 2 * (lane & 3);
        const float2 b2 = *(const float2*)(bn2 + col);
#pragma unroll
        for (int h = 0; h < 2; h++) {
            const int n = nb + rA + 8 * h;
            if (n < N) {
                float2 o;
                o.x = acc2[ct][2 * h + 0] + b2.x;
                o.y = acc2[ct][2 * h + 1] + b2.y;
                *(float2*)(out + (long long)n * DOUT + col) = o;
            }
        }
    }
}

// ---------------------------------------------------------------- tail copies
__global__ void tail_kernel(const int* __restrict__ ei,
                            const float* __restrict__ EF,
                            float* __restrict__ out,
                            long long offEI, long long nEI, long long nEF)
{
    const long long tid4 = (long long)blockIdx.x * blockDim.x + threadIdx.x;
    const long long stride = (long long)gridDim.x * blockDim.x;

    const long long nEI4 = nEI >> 2;
    const int4* ei4 = (const int4*)ei;
    for (long long i = tid4; i < nEI4; i += stride) {
        const int4 v = ei4[i];
        float4 f;
        f.x = (float)v.x; f.y = (float)v.y; f.z = (float)v.z; f.w = (float)v.w;
        *(float4*)(out + offEI + 4 * i) = f;
    }
    for (long long i = nEI4 * 4 + tid4; i < nEI; i += stride)
        out[offEI + i] = (float)ei[i];

    const long long offEF = offEI + nEI;
    const long long nEF4 = nEF >> 2;
    const float4* EF4 = (const float4*)EF;
    for (long long i = tid4; i < nEF4; i += stride)
        *(float4*)(out + offEF + 4 * i) = EF4[i];
    for (long long i = nEF4 * 4 + tid4; i < nEF; i += stride)
        out[offEF + i] = EF[i];
}

// ---------------------------------------------------------------- launch
extern "C" void kernel_launch(void* const* d_in, const int* in_sizes, int n_in,
                              void* d_out, int out_size)
{
    const float* X   = (const float*)d_in[0];
    const int*   ei  = (const int*)d_in[1];
    const float* EF  = (const float*)d_in[2];
    const float* We1 = (const float*)d_in[3];
    const float* be1 = (const float*)d_in[4];
    const float* We2 = (const float*)d_in[5];
    const float* be2 = (const float*)d_in[6];
    const float* Wa  = (const float*)d_in[7];
    const float* ba  = (const float*)d_in[8];
    const float* Wn1 = (const float*)d_in[9];
    const float* bn1 = (const float*)d_in[10];
    const float* Wn2 = (const float*)d_in[11];
    const float* bn2 = (const float*)d_in[12];

    const int N = in_sizes[0] / D;
    const int E = in_sizes[2] / DE;
    float* out = (float*)d_out;

    static int smem_set = 0;
    if (!smem_set) {
        cudaFuncSetAttribute(edge_kernel,
                             cudaFuncAttributeMaxDynamicSharedMemorySize, EDGE_SMEM);
        smem_set = 1;
    }

    setup_kernel<<<58, 256>>>(We1, We2, Wn1, Wn2);
    zero_agg_kernel<<<512, 256>>>(((long long)N * DOUT) / 4);
    precompute_kernel<<<(N + PNODES - 1) / PNODES, 128>>>(X, We1, be1, N);

    const int numTiles = (E + TE - 1) / TE;
    int grid = 444;
    if (grid > numTiles) grid = numTiles;
    edge_kernel<<<grid, 256, EDGE_SMEM>>>(ei, EF, Wa, ba, be2, N, E);

    node_kernel<<<(N + NT - 1) / NT, 256>>>(X, bn1, bn2, out, N);

    const long long n64 = (long long)N * DOUT;
    long long avail = (long long)out_size - n64;
    if (avail > 0) {
        long long nEI = 2LL * E;
        if (nEI > avail) nEI = avail;
        long long nEF = avail - nEI;
        const long long maxEF = (long long)E * DE;
        if (nEF > maxEF) nEF = maxEF;
        tail_kernel<<<2048, 256>>>(ei, EF, out, n64, nEI, nEF);
    }
}

// round 16
// speedup vs baseline: 3.9188x; 1.0488x over previous
#include <cuda_runtime.h>
#include <cuda_fp16.h>
#include <cuda_bf16.h>
#include <cstdint>

#define D     64
#define DE    16
#define HDIM  128
#define DOUT  64
#define MAXN  100000
#define TE    64

// Scratch (device globals — allocation-free contract)
__device__ __half g_Ph[(size_t)MAXN * HDIM];  // fp16: X @ We1[0:64] + be1
__device__ __half g_Qh[(size_t)MAXN * HDIM];  // fp16: X @ We1[64:128]
__device__ __half g_Xh[(size_t)MAXN * D];     // fp16 copy of X (attn gate)
__device__ float  g_agg[(size_t)MAXN * DOUT]; // segment sum

// Weight fragment tables, built once by setup_kernel
__device__ uint2 g_WfragEh[8 * 8 * 32];    // We2  [128][64]  fp16 m16n8k16 B-frags
__device__ uint2 g_WfragCh[16 * 32];       // W1c  [16][128]  fp16 m16n8k16 B-frags
__device__ uint2 g_WfragN1[16 * 16 * 32];  // Wn1  [128][128] tf32
__device__ uint2 g_WfragN2[16 * 8 * 32];   // Wn2  [128][64]  tf32

// ---- activations: single-MUFU via tanh.approx ----
__device__ __forceinline__ float siluf(float x) {
    const float h = 0.5f * x;
    float t;
    asm("tanh.approx.f32 %0, %1;" : "=f"(t) : "f"(h));
    return fmaf(h, t, h);               // x * sigmoid(x)
}
__device__ __forceinline__ float sigmoidf_(float x) {
    float t;
    asm("tanh.approx.f32 %0, %1;" : "=f"(t) : "f"(0.5f * x));
    return fmaf(0.5f, t, 0.5f);
}

// ---- helpers ----
__device__ __forceinline__ unsigned long long pk2(float x, float y) {
    unsigned long long r;
    asm("mov.b64 %0, {%1, %2};" : "=l"(r) : "f"(x), "f"(y));
    return r;
}
__device__ __forceinline__ unsigned long long fma2(unsigned long long a,
                                                   unsigned long long b,
                                                   unsigned long long c) {
    unsigned long long d;
    asm("fma.rn.f32x2 %0, %1, %2, %3;" : "=l"(d) : "l"(a), "l"(b), "l"(c));
    return d;
}
__device__ __forceinline__ float2 upk2(unsigned long long v) {
    float2 f;
    asm("mov.b64 {%0, %1}, %2;" : "=f"(f.x), "=f"(f.y) : "l"(v));
    return f;
}
__device__ __forceinline__ void red_add_v2(float* p, float a, float b) {
    asm volatile("red.global.add.v2.f32 [%0], {%1, %2};"
                 :: "l"(p), "f"(a), "f"(b) : "memory");
}
__device__ __forceinline__ uint32_t tf32b(float x) {
    uint32_t r;
    asm("cvt.rna.tf32.f32 %0, %1;" : "=r"(r) : "f"(x));
    return r;
}
__device__ __forceinline__ uint32_t h2u(float lo, float hi) {
    __half2 h = __floats2half2_rn(lo, hi);
    return *(uint32_t*)&h;
}
__device__ __forceinline__ void mma_tf32(float acc[4], uint32_t a0, uint32_t a1,
                                         uint32_t a2, uint32_t a3,
                                         uint32_t b0, uint32_t b1) {
    asm volatile(
        "mma.sync.aligned.m16n8k8.row.col.f32.tf32.tf32.f32 "
        "{%0,%1,%2,%3}, {%4,%5,%6,%7}, {%8,%9}, {%0,%1,%2,%3};"
        : "+f"(acc[0]), "+f"(acc[1]), "+f"(acc[2]), "+f"(acc[3])
        : "r"(a0), "r"(a1), "r"(a2), "r"(a3), "r"(b0), "r"(b1));
}
__device__ __forceinline__ void mma_f16(float acc[4], uint32_t a0, uint32_t a1,
                                        uint32_t a2, uint32_t a3,
                                        uint32_t b0, uint32_t b1) {
    asm volatile(
        "mma.sync.aligned.m16n8k16.row.col.f32.f16.f16.f32 "
        "{%0,%1,%2,%3}, {%4,%5,%6,%7}, {%8,%9}, {%0,%1,%2,%3};"
        : "+f"(acc[0]), "+f"(acc[1]), "+f"(acc[2]), "+f"(acc[3])
        : "r"(a0), "r"(a1), "r"(a2), "r"(a3), "r"(b0), "r"(b1));
}
__device__ __forceinline__ void ldsm4(uint32_t& r0, uint32_t& r1,
                                      uint32_t& r2, uint32_t& r3, uint32_t addr) {
    asm volatile("ldmatrix.sync.aligned.m8n8.x4.shared.b16 {%0,%1,%2,%3}, [%4];"
                 : "=r"(r0), "=r"(r1), "=r"(r2), "=r"(r3) : "r"(addr));
}
__device__ __forceinline__ void stsm4(uint32_t addr, uint32_t r0, uint32_t r1,
                                      uint32_t r2, uint32_t r3) {
    asm volatile("stmatrix.sync.aligned.m8n8.x4.shared.b16 [%0], {%1,%2,%3,%4};"
                 :: "r"(addr), "r"(r0), "r"(r1), "r"(r2), "r"(r3));
}
#define BAR_SYNC(id)   asm volatile("bar.sync %0, 256;"   :: "r"(id) : "memory")
#define BAR_ARRIVE(id) asm volatile("bar.arrive %0, 256;" :: "r"(id) : "memory")

// ---------------------------------------------------------------- setup: fragment tables
__global__ void setup_kernel(const float* __restrict__ We1, const float* __restrict__ We2,
                             const float* __restrict__ Wn1, const float* __restrict__ Wn2)
{
    const int idx = blockIdx.x * blockDim.x + threadIdx.x;

    if (idx < 8 * 8 * 32) {  // We2 -> fp16 E table (m16n8k16 B, col-major)
        const int lane = idx & 31, rest = idx >> 5;
        const int ks = rest >> 3, ct = rest & 7;
        const int n = 8 * ct + (lane >> 2);
        const int k0 = 16 * ks + 2 * (lane & 3);
        uint2 b;
        b.x = h2u(We2[k0 * DOUT + n],       We2[(k0 + 1) * DOUT + n]);
        b.y = h2u(We2[(k0 + 8) * DOUT + n], We2[(k0 + 9) * DOUT + n]);
        g_WfragEh[idx] = b;
    }
    const int i2 = idx - 2048;
    if (i2 >= 0 && i2 < 16 * 32) {  // W1c -> fp16 C table (single k16 step)
        const int lane = i2 & 31, ct = i2 >> 5;
        const int n = 8 * ct + (lane >> 2);
        const int k0 = 2 * (lane & 3);
        const float* W1c = We1 + 2 * D * HDIM;
        uint2 b;
        b.x = h2u(W1c[k0 * HDIM + n],       W1c[(k0 + 1) * HDIM + n]);
        b.y = h2u(W1c[(k0 + 8) * HDIM + n], W1c[(k0 + 9) * HDIM + n]);
        g_WfragCh[i2] = b;
    }
    const int i3 = idx - 2048 - 512;
    if (i3 >= 0 && i3 < 16 * 16 * 32) {  // Wn1 -> N1 table (tf32)
        const int lane = i3 & 31, kct = i3 >> 5;
        const int ks = kct >> 4, ct = kct & 15;
        const int k0 = 8 * ks + (lane & 3), n = 8 * ct + (lane >> 2);
        g_WfragN1[i3] = make_uint2(tf32b(Wn1[k0 * HDIM + n]),
                                   tf32b(Wn1[(k0 + 4) * HDIM + n]));
    }
    const int i4 = idx - 2048 - 512 - 8192;
    if (i4 >= 0 && i4 < 16 * 8 * 32) {  // Wn2 -> N2 table (tf32)
        const int lane = i4 & 31, kct = i4 >> 5;
        const int ks = kct >> 3, ct = kct & 7;
        const int k0 = 8 * ks + (lane & 3), n = 8 * ct + (lane >> 2);
        g_WfragN2[i4] = make_uint2(tf32b(Wn2[k0 * DOUT + n]),
                                   tf32b(Wn2[(k0 + 4) * DOUT + n]));
    }
}

// ---------------------------------------------------------------- zero agg
__global__ void zero_agg_kernel(long long n4) {
    long long i = (long long)blockIdx.x * blockDim.x + threadIdx.x;
    const long long stride = (long long)gridDim.x * blockDim.x;
    float4* p = (float4*)g_agg;
    const float4 z = make_float4(0.f, 0.f, 0.f, 0.f);
    for (; i < n4; i += stride) p[i] = z;
}

// ---------------------------------------------------- P/Q/Xh precompute (16 nodes/block)
#define PNODES 16
__global__ __launch_bounds__(128) void precompute_kernel(
    const float* __restrict__ X, const float* __restrict__ We1,
    const float* __restrict__ be1, int N)
{
    __shared__ float x_sh[D][PNODES + 2];
    const int t = threadIdx.x;
    const int nb = blockIdx.x * PNODES;

    for (int idx = t; idx < PNODES * D; idx += 128) {
        const int m = idx >> 6, k = idx & 63;
        const int n = nb + m;
        x_sh[k][m] = (n < N) ? X[(long long)n * D + k] : 0.f;
    }
    __syncthreads();

    for (int idx = t; idx < PNODES * D; idx += 128) {
        const int m = idx >> 6, k = idx & 63;
        const int n = nb + m;
        if (n < N) g_Xh[(long long)n * D + k] = __float2half_rn(x_sh[k][m]);
    }

    const float b = be1[t];
    unsigned long long accP[PNODES / 2], accQ[PNODES / 2];
#pragma unroll
    for (int mm = 0; mm < PNODES / 2; mm++) {
        accP[mm] = pk2(b, b);
        accQ[mm] = pk2(0.f, 0.f);
    }

#pragma unroll 4
    for (int k = 0; k < D; k++) {
        const float w1 = We1[k * HDIM + t];
        const float w2 = We1[(D + k) * HDIM + t];
        const unsigned long long w11 = pk2(w1, w1);
        const unsigned long long w22 = pk2(w2, w2);
#pragma unroll
        for (int mm = 0; mm < PNODES / 2; mm++) {
            const float2 xv = *(const float2*)&x_sh[k][2 * mm];
            const unsigned long long xx = pk2(xv.x, xv.y);
            accP[mm] = fma2(xx, w11, accP[mm]);
            accQ[mm] = fma2(xx, w22, accQ[mm]);
        }
    }
#pragma unroll
    for (int mm = 0; mm < PNODES / 2; mm++) {
        const float2 p = upk2(accP[mm]);
        const float2 q = upk2(accQ[mm]);
        const int n0 = nb + 2 * mm, n1 = n0 + 1;
        if (n0 < N) {
            g_Ph[(long long)n0 * HDIM + t] = __float2half_rn(p.x);
            g_Qh[(long long)n0 * HDIM + t] = __float2half_rn(q.x);
        }
        if (n1 < N) {
            g_Ph[(long long)n1 * HDIM + t] = __float2half_rn(p.y);
            g_Qh[(long long)n1 * HDIM + t] = __float2half_rn(q.y);
        }
    }
}

// ---------------------------------------------------------------- warp-specialized edge kernel
// A buffer rows are fp16 (half2 per uint32): 64 rows x 64 uint32 (+4 pad)
#define ASH 68
#define ABUF_U32 (64 * ASH)                 // 4352
#define OFF_ATTN (2 * ABUF_U32)             // 8704
#define OFF_FI   (OFF_ATTN + 2 * 64)        // 8832
#define EDGE_SMEM ((OFF_FI + 2 * 64) * 4)   // 35840 B

__global__ __launch_bounds__(256, 3) void edge_kernel(
    const int* __restrict__ ei, const float* __restrict__ EF,
    const float* __restrict__ Wa, const float* __restrict__ ba,
    const float* __restrict__ be2, int N, int E)
{
    extern __shared__ uint32_t sm[];

    const int tid  = threadIdx.x;
    const int lane = tid & 31;
    const int warp = tid >> 5;
    const int numTiles = (E + TE - 1) / TE;

    if (warp < 4) {
        // ======================= PRODUCERS =======================
        const float2 wa2 = ((const float2*)Wa)[lane];
        const float  ba0 = ba[0];
        int it = 0;
        for (int tile = blockIdx.x; tile < numTiles; tile += gridDim.x, it++) {
            const int b = it & 1;
            uint32_t* A    = sm + b * ABUF_U32;
            uint32_t* attn = sm + OFF_ATTN + b * 64;
            uint32_t* fi   = sm + OFF_FI + b * 64;
            if (it >= 2) BAR_SYNC(3 + b);
            const int base = tile * TE;

#pragma unroll
            for (int b8 = 0; b8 < 2; b8++) {
                const int s0 = warp * 16 + b8 * 8;
                int ii[8], jj[8];
#pragma unroll
                for (int s = 0; s < 8; s++) {
                    int e = base + s0 + s;
                    if (e >= E) e = 0;
                    ii[s] = ei[e];
                    jj[s] = ei[E + e];
                }
                uint2 pv[8], qv[8];
                uint32_t xiv[8], xjv[8];
#pragma unroll
                for (int s = 0; s < 8; s++) {
                    pv[s] = ((const uint2*)(g_Ph + (long long)ii[s] * HDIM))[lane];
                    qv[s] = ((const uint2*)(g_Qh + (long long)jj[s] * HDIM))[lane];
                }
#pragma unroll
                for (int s = 0; s < 8; s++) {
                    xiv[s] = ((const uint32_t*)(g_Xh + (long long)ii[s] * D))[lane];
                    xjv[s] = ((const uint32_t*)(g_Xh + (long long)jj[s] * D))[lane];
                }
#pragma unroll
                for (int s = 0; s < 8; s++) {
                    const int row = s0 + s;
                    uint2 a;
                    __half2 a01 = __hadd2(*(const __half2*)&pv[s].x, *(const __half2*)&qv[s].x);
                    __half2 a23 = __hadd2(*(const __half2*)&pv[s].y, *(const __half2*)&qv[s].y);
                    a.x = *(uint32_t*)&a01;
                    a.y = *(uint32_t*)&a23;
                    *(uint2*)&A[row * ASH + 2 * lane] = a;

                    const float2 xi = __half22float2(*(const __half2*)&xiv[s]);
                    const float2 xj = __half22float2(*(const __half2*)&xjv[s]);
                    float p = fabsf(xi.x - xj.x) * wa2.x + fabsf(xi.y - xj.y) * wa2.y;
#pragma unroll
                    for (int off = 16; off > 0; off >>= 1)
                        p += __shfl_down_sync(0xffffffffu, p, off);
                    if (lane == 0) {
                        const int e = base + row;
                        attn[row] = __float_as_uint((e < E) ? sigmoidf_(p + ba0) : 0.f);
                        fi[row]   = (uint32_t)ii[s];
                    }
                }
            }
            __threadfence_block();
            BAR_ARRIVE(1 + b);
        }
    } else {
        // ======================= CONSUMERS =======================
        const int cw = warp - 4;
        const int r0 = 16 * cw;
        float2 bb[8];
#pragma unroll
        for (int ct = 0; ct < 8; ct++)
            bb[ct] = *(const float2*)(be2 + 8 * ct + 2 * (lane & 3));

        const float2* EF2 = (const float2*)EF;
        const int rA = r0 + (lane >> 2);
        // ldmatrix base offset (bytes) for this lane within the A tile
        const uint32_t lrow = r0 + (lane & 7) + ((lane >> 3) & 1) * 8;
        const uint32_t lcol16 = (lane >> 4) * 16;

        int it = 0;
        for (int tile = blockIdx.x; tile < numTiles; tile += gridDim.x, it++) {
            const int b = it & 1;
            uint32_t* A    = sm + b * ABUF_U32;
            uint32_t* attn = sm + OFF_ATTN + b * 64;
            uint32_t* fi   = sm + OFF_FI + b * 64;
            BAR_SYNC(1 + b);
            const int base = tile * TE;

            const uint32_t smA = (uint32_t)__cvta_generic_to_shared(A);
            const uint32_t ldsmBase = smA + lrow * (ASH * 4) + lcol16;

            // ---- EF A-fragment from global (coalesced float2) ----
            int e0 = base + rA;     if (e0 >= E) e0 = E - 1;
            int e1 = base + rA + 8; if (e1 >= E) e1 = E - 1;
            const int c4 = lane & 3;
            const float2 f00 = __ldg(EF2 + (long long)e0 * 8 + c4);
            const float2 f10 = __ldg(EF2 + (long long)e1 * 8 + c4);
            const float2 f01 = __ldg(EF2 + (long long)e0 * 8 + 4 + c4);
            const float2 f11 = __ldg(EF2 + (long long)e1 * 8 + 4 + c4);
            const uint32_t ea0 = h2u(f00.x, f00.y);
            const uint32_t ea1 = h2u(f10.x, f10.y);
            const uint32_t ea2 = h2u(f01.x, f01.y);
            const uint32_t ea3 = h2u(f11.x, f11.y);

            // ---- stage A: acc = PQ + EF@W1c, silu, write back as fp16 ----
#pragma unroll
            for (int hf = 0; hf < 2; hf++) {
                float acc2[8][4];
#pragma unroll
                for (int ct2 = 0; ct2 < 4; ct2++) {
                    uint32_t v0, v1, v2, v3;
                    ldsm4(v0, v1, v2, v3, ldsmBase + 128 * hf + 32 * ct2);
                    const float2 g0 = __half22float2(*(const __half2*)&v0);
                    const float2 g1 = __half22float2(*(const __half2*)&v1);
                    const float2 g2 = __half22float2(*(const __half2*)&v2);
                    const float2 g3 = __half22float2(*(const __half2*)&v3);
                    acc2[2 * ct2][0] = g0.x; acc2[2 * ct2][1] = g0.y;
                    acc2[2 * ct2][2] = g1.x; acc2[2 * ct2][3] = g1.y;
                    acc2[2 * ct2 + 1][0] = g2.x; acc2[2 * ct2 + 1][1] = g2.y;
                    acc2[2 * ct2 + 1][2] = g3.x; acc2[2 * ct2 + 1][3] = g3.y;
                }
#pragma unroll
                for (int ct = 0; ct < 8; ct++) {
                    const uint2 B = g_WfragCh[(8 * hf + ct) * 32 + lane];
                    mma_f16(acc2[ct], ea0, ea1, ea2, ea3, B.x, B.y);
                }
#pragma unroll
                for (int ct2 = 0; ct2 < 4; ct2++) {
                    const uint32_t w0 = h2u(siluf(acc2[2 * ct2][0]), siluf(acc2[2 * ct2][1]));
                    const uint32_t w1 = h2u(siluf(acc2[2 * ct2][2]), siluf(acc2[2 * ct2][3]));
                    const uint32_t w2 = h2u(siluf(acc2[2 * ct2 + 1][0]), siluf(acc2[2 * ct2 + 1][1]));
                    const uint32_t w3 = h2u(siluf(acc2[2 * ct2 + 1][2]), siluf(acc2[2 * ct2 + 1][3]));
                    stsm4(ldsmBase + 128 * hf + 32 * ct2, w0, w1, w2, w3);
                }
            }
            __syncwarp();

            // ---- main GEMM: 16 rows x 64 cols x 128 k (fp16, 8 k-steps) ----
            float acc[8][4];
#pragma unroll
            for (int ct = 0; ct < 8; ct++)
#pragma unroll
                for (int u = 0; u < 4; u++) acc[ct][u] = 0.f;

#pragma unroll
            for (int ks = 0; ks < 8; ks++) {
                uint32_t a0, a1, a2, a3;
                ldsm4(a0, a1, a2, a3, ldsmBase + 32 * ks);
#pragma unroll
                for (int ct = 0; ct < 8; ct++) {
                    const uint2 B = g_WfragEh[(ks * 8 + ct) * 32 + lane];
                    mma_f16(acc[ct], a0, a1, a2, a3, B.x, B.y);
                }
            }

            // ---- epilogue: silu(acc + be2) * attn -> red scatter ----
#pragma unroll
            for (int h = 0; h < 2; h++) {
                const int eL = rA + 8 * h;
                if (base + eL < E) {
                    const float at = __uint_as_float(attn[eL]);
                    float* aggp = g_agg + (long long)(int)fi[eL] * DOUT;
#pragma unroll
                    for (int ct = 0; ct < 8; ct++) {
                        const int col = 8 * ct + 2 * (lane & 3);
                        red_add_v2(aggp + col,
                                   siluf(acc[ct][2 * h + 0] + bb[ct].x) * at,
                                   siluf(acc[ct][2 * h + 1] + bb[ct].y) * at);
                    }
                }
            }
            __threadfence_block();
            BAR_ARRIVE(3 + b);
        }
    }
}

// ---------------------------------------------------------------- node MLP: tf32 MMA
#define NT 64
#define NSTRIDE 132
__global__ __launch_bounds__(256) void node_kernel(
    const float* __restrict__ X, const float* __restrict__ bn1,
    const float* __restrict__ bn2, float* __restrict__ out, int N)
{
    __shared__ uint32_t in_sh[NT][NSTRIDE];
    __shared__ uint32_t hid_sh[NT][NSTRIDE];
    const int tid  = threadIdx.x;
    const int lane = tid & 31;
    const int warp = tid >> 5;
    const int nb   = blockIdx.x * NT;

    for (int i = tid; i < NT * 32; i += 256) {
        const int r = i >> 5, c = i & 31;
        const int n = nb + r;
        float4 v = make_float4(0.f, 0.f, 0.f, 0.f);
        if (n < N) {
            v = (c < 16) ? ((const float4*)X)[(long long)n * 16 + c]
                         : ((const float4*)g_agg)[(long long)n * 16 + (c - 16)];
        }
        uint4 u;
        u.x = tf32b(v.x); u.y = tf32b(v.y); u.z = tf32b(v.z); u.w = tf32b(v.w);
        *(uint4*)&in_sh[r][4 * c] = u;
    }
    __syncthreads();

    const int rg   = warp >> 1;
    const int half = warp & 1;
    const int r0   = 16 * rg;
    const int rA   = r0 + (lane >> 2);

    float acc[8][4];
#pragma unroll
    for (int ct = 0; ct < 8; ct++)
#pragma unroll
        for (int u = 0; u < 4; u++) acc[ct][u] = 0.f;

#pragma unroll
    for (int ks = 0; ks < 16; ks++) {
        const int acol = 8 * ks + (lane & 3);
        const uint32_t a0 = in_sh[rA][acol];
        const uint32_t a1 = in_sh[rA + 8][acol];
        const uint32_t a2 = in_sh[rA][acol + 4];
        const uint32_t a3 = in_sh[rA + 8][acol + 4];
#pragma unroll
        for (int ct = 0; ct < 8; ct++) {
            const uint2 B = g_WfragN1[(ks * 16 + 8 * half + ct) * 32 + lane];
            mma_tf32(acc[ct], a0, a1, a2, a3, B.x, B.y);
        }
    }
#pragma unroll
    for (int ct = 0; ct < 8; ct++) {
        const int col = 8 * (8 * half + ct) + 2 * (lane & 3);
        const float2 b1 = *(const float2*)(bn1 + col);
        uint2 u0, u1;
        u0.x = tf32b(siluf(acc[ct][0] + b1.x));
        u0.y = tf32b(siluf(acc[ct][1] + b1.y));
        u1.x = tf32b(siluf(acc[ct][2] + b1.x));
        u1.y = tf32b(siluf(acc[ct][3] + b1.y));
        *(uint2*)&hid_sh[rA][col] = u0;
        *(uint2*)&hid_sh[rA + 8][col] = u1;
    }
    __syncthreads();

    float acc2[4][4];
#pragma unroll
    for (int ct = 0; ct < 4; ct++)
#pragma unroll
        for (int u = 0; u < 4; u++) acc2[ct][u] = 0.f;

#pragma unroll
    for (int ks = 0; ks < 16; ks++) {
        const int acol = 8 * ks + (lane & 3);
        const uint32_t a0 = hid_sh[rA][acol];
        const uint32_t a1 = hid_sh[rA + 8][acol];
        const uint32_t a2 = hid_sh[rA][acol + 4];
        const uint32_t a3 = hid_sh[rA + 8][acol + 4];
#pragma unroll
        for (int ct = 0; ct < 4; ct++) {
            const uint2 B = g_WfragN2[(ks * 8 + 4 * half + ct) * 32 + lane];
            mma_tf32(acc2[ct], a0, a1, a2, a3, B.x, B.y);
        }
    }
#pragma unroll
    for (int ct = 0; ct < 4; ct++) {
        const int col = 8 * (4 * half + ct) + 2 * (lane & 3);
        const float2 b2 = *(const float2*)(bn2 + col);
#pragma unroll
        for (int h = 0; h < 2; h++) {
            const int n = nb + rA + 8 * h;
            if (n < N) {
                float2 o;
                o.x = acc2[ct][2 * h + 0] + b2.x;
                o.y = acc2[ct][2 * h + 1] + b2.y;
                *(float2*)(out + (long long)n * DOUT + col) = o;
            }
        }
    }
}

// ---------------------------------------------------------------- tail copies
__global__ void tail_kernel(const int* __restrict__ ei,
                            const float* __restrict__ EF,
                            float* __restrict__ out,
                            long long offEI, long long nEI, long long nEF)
{
    const long long tid4 = (long long)blockIdx.x * blockDim.x + threadIdx.x;
    const long long stride = (long long)gridDim.x * blockDim.x;

    const long long nEI4 = nEI >> 2;
    const int4* ei4 = (const int4*)ei;
    for (long long i = tid4; i < nEI4; i += stride) {
        const int4 v = ei4[i];
        float4 f;
        f.x = (float)v.x; f.y = (float)v.y; f.z = (float)v.z; f.w = (float)v.w;
        *(float4*)(out + offEI + 4 * i) = f;
    }
    for (long long i = nEI4 * 4 + tid4; i < nEI; i += stride)
        out[offEI + i] = (float)ei[i];

    const long long offEF = offEI + nEI;
    const long long nEF4 = nEF >> 2;
    const float4* EF4 = (const float4*)EF;
    for (long long i = tid4; i < nEF4; i += stride)
        *(float4*)(out + offEF + 4 * i) = EF4[i];
    for (long long i = nEF4 * 4 + tid4; i < nEF; i += stride)
        out[offEF + i] = EF[i];
}

// ---------------------------------------------------------------- launch
extern "C" void kernel_launch(void* const* d_in, const int* in_sizes, int n_in,
                              void* d_out, int out_size)
{
    const float* X   = (const float*)d_in[0];
    const int*   ei  = (const int*)d_in[1];
    const float* EF  = (const float*)d_in[2];
    const float* We1 = (const float*)d_in[3];
    const float* be1 = (const float*)d_in[4];
    const float* We2 = (const float*)d_in[5];
    const float* be2 = (const float*)d_in[6];
    const float* Wa  = (const float*)d_in[7];
    const float* ba  = (const float*)d_in[8];
    const float* Wn1 = (const float*)d_in[9];
    const float* bn1 = (const float*)d_in[10];
    const float* Wn2 = (const float*)d_in[11];
    const float* bn2 = (const float*)d_in[12];

    const int N = in_sizes[0] / D;
    const int E = in_sizes[2] / DE;
    float* out = (float*)d_out;

    static int smem_set = 0;
    if (!smem_set) {
        cudaFuncSetAttribute(edge_kernel,
                             cudaFuncAttributeMaxDynamicSharedMemorySize, EDGE_SMEM);
        smem_set = 1;
    }

    setup_kernel<<<58, 256>>>(We1, We2, Wn1, Wn2);
    zero_agg_kernel<<<512, 256>>>(((long long)N * DOUT) / 4);
    precompute_kernel<<<(N + PNODES - 1) / PNODES, 128>>>(X, We1, be1, N);

    const int numTiles = (E + TE - 1) / TE;
    int grid = 444;
    if (grid > numTiles) grid = numTiles;
    edge_kernel<<<grid, 256, EDGE_SMEM>>>(ei, EF, Wa, ba, be2, N, E);

    node_kernel<<<(N + NT - 1) / NT, 256>>>(X, bn1, bn2, out, N);

    const long long n64 = (long long)N * DOUT;
    long long avail = (long long)out_size - n64;
    if (avail > 0) {
        long long nEI = 2LL * E;
        if (nEI > avail) nEI = avail;
        long long nEF = avail - nEI;
        const long long maxEF = (long long)E * DE;
        if (nEF > maxEF) nEF = maxEF;
        tail_kernel<<<2048, 256>>>(ei, EF, out, n64, nEI, nEF);
    }
}

// round 17
// speedup vs baseline: 4.1096x; 1.0487x over previous
#include <cuda_runtime.h>
#include <cuda_fp16.h>
#include <cuda_bf16.h>
#include <cstdint>

#define D     64
#define DE    16
#define HDIM  128
#define DOUT  64
#define MAXN  100000
#define TE    64

// Scratch (device globals — allocation-free contract)
__device__ __half g_Ph[(size_t)MAXN * HDIM];  // fp16: X @ We1[0:64] + be1
__device__ __half g_Qh[(size_t)MAXN * HDIM];  // fp16: X @ We1[64:128]
__device__ __half g_Xh[(size_t)MAXN * D];     // fp16 copy of X (attn gate)
__device__ float  g_agg[(size_t)MAXN * DOUT]; // segment sum

// Weight fragment tables, built once by setup_kernel
__device__ uint2 g_WfragEh[8 * 8 * 32];    // We2  [128][64]  fp16 m16n8k16 B-frags
__device__ uint2 g_WfragCh[16 * 32];       // W1c  [16][128]  fp16 m16n8k16 B-frags
__device__ uint2 g_WfragN1[16 * 16 * 32];  // Wn1  [128][128] tf32
__device__ uint2 g_WfragN2[16 * 8 * 32];   // Wn2  [128][64]  tf32

// ---- activations: single-MUFU via tanh.approx ----
__device__ __forceinline__ float siluf(float x) {
    const float h = 0.5f * x;
    float t;
    asm("tanh.approx.f32 %0, %1;" : "=f"(t) : "f"(h));
    return fmaf(h, t, h);               // x * sigmoid(x)
}
__device__ __forceinline__ float sigmoidf_(float x) {
    float t;
    asm("tanh.approx.f32 %0, %1;" : "=f"(t) : "f"(0.5f * x));
    return fmaf(0.5f, t, 0.5f);
}

// ---- helpers ----
__device__ __forceinline__ unsigned long long pk2(float x, float y) {
    unsigned long long r;
    asm("mov.b64 %0, {%1, %2};" : "=l"(r) : "f"(x), "f"(y));
    return r;
}
__device__ __forceinline__ unsigned long long fma2(unsigned long long a,
                                                   unsigned long long b,
                                                   unsigned long long c) {
    unsigned long long d;
    asm("fma.rn.f32x2 %0, %1, %2, %3;" : "=l"(d) : "l"(a), "l"(b), "l"(c));
    return d;
}
__device__ __forceinline__ float2 upk2(unsigned long long v) {
    float2 f;
    asm("mov.b64 {%0, %1}, %2;" : "=f"(f.x), "=f"(f.y) : "l"(v));
    return f;
}
__device__ __forceinline__ void red_add_v2(float* p, float a, float b) {
    asm volatile("red.global.add.v2.f32 [%0], {%1, %2};"
                 :: "l"(p), "f"(a), "f"(b) : "memory");
}
__device__ __forceinline__ uint32_t tf32b(float x) {
    uint32_t r;
    asm("cvt.rna.tf32.f32 %0, %1;" : "=r"(r) : "f"(x));
    return r;
}
__device__ __forceinline__ uint32_t h2u(float lo, float hi) {
    __half2 h = __floats2half2_rn(lo, hi);
    return *(uint32_t*)&h;
}
__device__ __forceinline__ void mma_tf32(float acc[4], uint32_t a0, uint32_t a1,
                                         uint32_t a2, uint32_t a3,
                                         uint32_t b0, uint32_t b1) {
    asm volatile(
        "mma.sync.aligned.m16n8k8.row.col.f32.tf32.tf32.f32 "
        "{%0,%1,%2,%3}, {%4,%5,%6,%7}, {%8,%9}, {%0,%1,%2,%3};"
        : "+f"(acc[0]), "+f"(acc[1]), "+f"(acc[2]), "+f"(acc[3])
        : "r"(a0), "r"(a1), "r"(a2), "r"(a3), "r"(b0), "r"(b1));
}
__device__ __forceinline__ void mma_f16(float acc[4], uint32_t a0, uint32_t a1,
                                        uint32_t a2, uint32_t a3,
                                        uint32_t b0, uint32_t b1) {
    asm volatile(
        "mma.sync.aligned.m16n8k16.row.col.f32.f16.f16.f32 "
        "{%0,%1,%2,%3}, {%4,%5,%6,%7}, {%8,%9}, {%0,%1,%2,%3};"
        : "+f"(acc[0]), "+f"(acc[1]), "+f"(acc[2]), "+f"(acc[3])
        : "r"(a0), "r"(a1), "r"(a2), "r"(a3), "r"(b0), "r"(b1));
}
__device__ __forceinline__ void ldsm4(uint32_t& r0, uint32_t& r1,
                                      uint32_t& r2, uint32_t& r3, uint32_t addr) {
    asm volatile("ldmatrix.sync.aligned.m8n8.x4.shared.b16 {%0,%1,%2,%3}, [%4];"
                 : "=r"(r0), "=r"(r1), "=r"(r2), "=r"(r3) : "r"(addr));
}
#define BAR_SYNC(id)   asm volatile("bar.sync %0, 256;"   :: "r"(id) : "memory")
#define BAR_ARRIVE(id) asm volatile("bar.arrive %0, 256;" :: "r"(id) : "memory")

// ---------------------------------------------------------------- setup: fragment tables
__global__ void setup_kernel(const float* __restrict__ We1, const float* __restrict__ We2,
                             const float* __restrict__ Wn1, const float* __restrict__ Wn2)
{
    const int idx = blockIdx.x * blockDim.x + threadIdx.x;

    if (idx < 8 * 8 * 32) {  // We2 -> fp16 E table (m16n8k16 B, col-major)
        const int lane = idx & 31, rest = idx >> 5;
        const int ks = rest >> 3, ct = rest & 7;
        const int n = 8 * ct + (lane >> 2);
        const int k0 = 16 * ks + 2 * (lane & 3);
        uint2 b;
        b.x = h2u(We2[k0 * DOUT + n],       We2[(k0 + 1) * DOUT + n]);
        b.y = h2u(We2[(k0 + 8) * DOUT + n], We2[(k0 + 9) * DOUT + n]);
        g_WfragEh[idx] = b;
    }
    const int i2 = idx - 2048;
    if (i2 >= 0 && i2 < 16 * 32) {  // W1c -> fp16 C table (single k16 step)
        const int lane = i2 & 31, ct = i2 >> 5;
        const int n = 8 * ct + (lane >> 2);
        const int k0 = 2 * (lane & 3);
        const float* W1c = We1 + 2 * D * HDIM;
        uint2 b;
        b.x = h2u(W1c[k0 * HDIM + n],       W1c[(k0 + 1) * HDIM + n]);
        b.y = h2u(W1c[(k0 + 8) * HDIM + n], W1c[(k0 + 9) * HDIM + n]);
        g_WfragCh[i2] = b;
    }
    const int i3 = idx - 2048 - 512;
    if (i3 >= 0 && i3 < 16 * 16 * 32) {  // Wn1 -> N1 table (tf32)
        const int lane = i3 & 31, kct = i3 >> 5;
        const int ks = kct >> 4, ct = kct & 15;
        const int k0 = 8 * ks + (lane & 3), n = 8 * ct + (lane >> 2);
        g_WfragN1[i3] = make_uint2(tf32b(Wn1[k0 * HDIM + n]),
                                   tf32b(Wn1[(k0 + 4) * HDIM + n]));
    }
    const int i4 = idx - 2048 - 512 - 8192;
    if (i4 >= 0 && i4 < 16 * 8 * 32) {  // Wn2 -> N2 table (tf32)
        const int lane = i4 & 31, kct = i4 >> 5;
        const int ks = kct >> 3, ct = kct & 7;
        const int k0 = 8 * ks + (lane & 3), n = 8 * ct + (lane >> 2);
        g_WfragN2[i4] = make_uint2(tf32b(Wn2[k0 * DOUT + n]),
                                   tf32b(Wn2[(k0 + 4) * DOUT + n]));
    }
}

// ---------------------------------------------------------------- zero agg
__global__ void zero_agg_kernel(long long n4) {
    long long i = (long long)blockIdx.x * blockDim.x + threadIdx.x;
    const long long stride = (long long)gridDim.x * blockDim.x;
    float4* p = (float4*)g_agg;
    const float4 z = make_float4(0.f, 0.f, 0.f, 0.f);
    for (; i < n4; i += stride) p[i] = z;
}

// ---------------------------------------------------- P/Q/Xh precompute (16 nodes/block)
#define PNODES 16
__global__ __launch_bounds__(128) void precompute_kernel(
    const float* __restrict__ X, const float* __restrict__ We1,
    const float* __restrict__ be1, int N)
{
    __shared__ float x_sh[D][PNODES + 2];
    const int t = threadIdx.x;
    const int nb = blockIdx.x * PNODES;

    for (int idx = t; idx < PNODES * D; idx += 128) {
        const int m = idx >> 6, k = idx & 63;
        const int n = nb + m;
        x_sh[k][m] = (n < N) ? X[(long long)n * D + k] : 0.f;
    }
    __syncthreads();

    for (int idx = t; idx < PNODES * D; idx += 128) {
        const int m = idx >> 6, k = idx & 63;
        const int n = nb + m;
        if (n < N) g_Xh[(long long)n * D + k] = __float2half_rn(x_sh[k][m]);
    }

    const float b = be1[t];
    unsigned long long accP[PNODES / 2], accQ[PNODES / 2];
#pragma unroll
    for (int mm = 0; mm < PNODES / 2; mm++) {
        accP[mm] = pk2(b, b);
        accQ[mm] = pk2(0.f, 0.f);
    }

#pragma unroll 4
    for (int k = 0; k < D; k++) {
        const float w1 = We1[k * HDIM + t];
        const float w2 = We1[(D + k) * HDIM + t];
        const unsigned long long w11 = pk2(w1, w1);
        const unsigned long long w22 = pk2(w2, w2);
#pragma unroll
        for (int mm = 0; mm < PNODES / 2; mm++) {
            const float2 xv = *(const float2*)&x_sh[k][2 * mm];
            const unsigned long long xx = pk2(xv.x, xv.y);
            accP[mm] = fma2(xx, w11, accP[mm]);
            accQ[mm] = fma2(xx, w22, accQ[mm]);
        }
    }
#pragma unroll
    for (int mm = 0; mm < PNODES / 2; mm++) {
        const float2 p = upk2(accP[mm]);
        const float2 q = upk2(accQ[mm]);
        const int n0 = nb + 2 * mm, n1 = n0 + 1;
        if (n0 < N) {
            g_Ph[(long long)n0 * HDIM + t] = __float2half_rn(p.x);
            g_Qh[(long long)n0 * HDIM + t] = __float2half_rn(q.x);
        }
        if (n1 < N) {
            g_Ph[(long long)n1 * HDIM + t] = __float2half_rn(p.y);
            g_Qh[(long long)n1 * HDIM + t] = __float2half_rn(q.y);
        }
    }
}

// ---------------------------------------------------------------- warp-specialized edge kernel
// A buffer rows are fp16 (half2 per uint32): 64 rows x 64 uint32 (+4 pad)
#define ASH 68
#define ABUF_U32 (64 * ASH)                 // 4352
#define OFF_ATTN (2 * ABUF_U32)             // 8704
#define OFF_FI   (OFF_ATTN + 2 * 64)        // 8832
#define EDGE_SMEM ((OFF_FI + 2 * 64) * 4)   // 35840 B

__global__ __launch_bounds__(256, 3) void edge_kernel(
    const int* __restrict__ ei, const float* __restrict__ EF,
    const float* __restrict__ Wa, const float* __restrict__ ba,
    const float* __restrict__ be2, int N, int E)
{
    extern __shared__ uint32_t sm[];

    const int tid  = threadIdx.x;
    const int lane = tid & 31;
    const int warp = tid >> 5;
    const int numTiles = (E + TE - 1) / TE;

    if (warp < 4) {
        // ======================= PRODUCERS =======================
        const float2 wa2 = ((const float2*)Wa)[lane];
        const float  ba0 = ba[0];
        int it = 0;
        for (int tile = blockIdx.x; tile < numTiles; tile += gridDim.x, it++) {
            const int b = it & 1;
            uint32_t* A    = sm + b * ABUF_U32;
            uint32_t* attn = sm + OFF_ATTN + b * 64;
            uint32_t* fi   = sm + OFF_FI + b * 64;
            if (it >= 2) BAR_SYNC(3 + b);
            const int base = tile * TE;

#pragma unroll
            for (int b8 = 0; b8 < 2; b8++) {
                const int s0 = warp * 16 + b8 * 8;
                int ii[8], jj[8];
#pragma unroll
                for (int s = 0; s < 8; s++) {
                    int e = base + s0 + s;
                    if (e >= E) e = 0;
                    ii[s] = ei[e];
                    jj[s] = ei[E + e];
                }
                uint2 pv[8], qv[8];
                uint32_t xiv[8], xjv[8];
#pragma unroll
                for (int s = 0; s < 8; s++) {
                    pv[s] = ((const uint2*)(g_Ph + (long long)ii[s] * HDIM))[lane];
                    qv[s] = ((const uint2*)(g_Qh + (long long)jj[s] * HDIM))[lane];
                }
#pragma unroll
                for (int s = 0; s < 8; s++) {
                    xiv[s] = ((const uint32_t*)(g_Xh + (long long)ii[s] * D))[lane];
                    xjv[s] = ((const uint32_t*)(g_Xh + (long long)jj[s] * D))[lane];
                }
#pragma unroll
                for (int s = 0; s < 8; s++) {
                    const int row = s0 + s;
                    uint2 a;
                    __half2 a01 = __hadd2(*(const __half2*)&pv[s].x, *(const __half2*)&qv[s].x);
                    __half2 a23 = __hadd2(*(const __half2*)&pv[s].y, *(const __half2*)&qv[s].y);
                    a.x = *(uint32_t*)&a01;
                    a.y = *(uint32_t*)&a23;
                    *(uint2*)&A[row * ASH + 2 * lane] = a;

                    const float2 xi = __half22float2(*(const __half2*)&xiv[s]);
                    const float2 xj = __half22float2(*(const __half2*)&xjv[s]);
                    float p = fabsf(xi.x - xj.x) * wa2.x + fabsf(xi.y - xj.y) * wa2.y;
#pragma unroll
                    for (int off = 16; off > 0; off >>= 1)
                        p += __shfl_down_sync(0xffffffffu, p, off);
                    if (lane == 0) {
                        const int e = base + row;
                        attn[row] = __float_as_uint((e < E) ? sigmoidf_(p + ba0) : 0.f);
                        fi[row]   = (uint32_t)ii[s];
                    }
                }
            }
            __threadfence_block();
            BAR_ARRIVE(1 + b);
        }
    } else {
        // ======================= CONSUMERS =======================
        const int cw = warp - 4;
        const int r0 = 16 * cw;
        float2 bb[8];
#pragma unroll
        for (int ct = 0; ct < 8; ct++)
            bb[ct] = *(const float2*)(be2 + 8 * ct + 2 * (lane & 3));

        const float2* EF2 = (const float2*)EF;
        const int rA = r0 + (lane >> 2);
        // ldmatrix base offset (bytes) for this lane within the A tile
        const uint32_t lrow = r0 + (lane & 7) + ((lane >> 3) & 1) * 8;
        const uint32_t lcol16 = (lane >> 4) * 16;

        int it = 0;
        for (int tile = blockIdx.x; tile < numTiles; tile += gridDim.x, it++) {
            const int b = it & 1;
            uint32_t* A    = sm + b * ABUF_U32;
            uint32_t* attn = sm + OFF_ATTN + b * 64;
            uint32_t* fi   = sm + OFF_FI + b * 64;
            BAR_SYNC(1 + b);
            const int base = tile * TE;

            const uint32_t smA = (uint32_t)__cvta_generic_to_shared(A);
            const uint32_t ldsmBase = smA + lrow * (ASH * 4) + lcol16;

            // ---- EF A-fragment from global (coalesced float2) ----
            int e0 = base + rA;     if (e0 >= E) e0 = E - 1;
            int e1 = base + rA + 8; if (e1 >= E) e1 = E - 1;
            const int c4 = lane & 3;
            const float2 f00 = __ldg(EF2 + (long long)e0 * 8 + c4);
            const float2 f10 = __ldg(EF2 + (long long)e1 * 8 + c4);
            const float2 f01 = __ldg(EF2 + (long long)e0 * 8 + 4 + c4);
            const float2 f11 = __ldg(EF2 + (long long)e1 * 8 + 4 + c4);
            const uint32_t ea0 = h2u(f00.x, f00.y);
            const uint32_t ea1 = h2u(f10.x, f10.y);
            const uint32_t ea2 = h2u(f01.x, f01.y);
            const uint32_t ea3 = h2u(f11.x, f11.y);

            // ---- fused stage-A + main GEMM ----
            // Stage-A C-fragments (silu'd, fp16-packed) ARE the main-GEMM
            // A-fragments: acc2[2k].pack = a0/a1, acc2[2k+1].pack = a2/a3.
            float acc[8][4];
#pragma unroll
            for (int ct = 0; ct < 8; ct++)
#pragma unroll
                for (int u = 0; u < 4; u++) acc[ct][u] = 0.f;

#pragma unroll
            for (int hf = 0; hf < 2; hf++) {
                uint2 frag[8];   // frag[ct] = {rows rA pair, rows rA+8 pair} fp16
#pragma unroll
                for (int ct2 = 0; ct2 < 4; ct2++) {
                    uint32_t v0, v1, v2, v3;
                    ldsm4(v0, v1, v2, v3, ldsmBase + 128 * hf + 32 * ct2);
                    float acc2a[4], acc2b[4];
                    {
                        const float2 g0 = __half22float2(*(const __half2*)&v0);
                        const float2 g1 = __half22float2(*(const __half2*)&v1);
                        const float2 g2 = __half22float2(*(const __half2*)&v2);
                        const float2 g3 = __half22float2(*(const __half2*)&v3);
                        acc2a[0] = g0.x; acc2a[1] = g0.y; acc2a[2] = g1.x; acc2a[3] = g1.y;
                        acc2b[0] = g2.x; acc2b[1] = g2.y; acc2b[2] = g3.x; acc2b[3] = g3.y;
                    }
                    {
                        const uint2 B = g_WfragCh[(8 * hf + 2 * ct2) * 32 + lane];
                        mma_f16(acc2a, ea0, ea1, ea2, ea3, B.x, B.y);
                    }
                    {
                        const uint2 B = g_WfragCh[(8 * hf + 2 * ct2 + 1) * 32 + lane];
                        mma_f16(acc2b, ea0, ea1, ea2, ea3, B.x, B.y);
                    }
                    frag[2 * ct2].x     = h2u(siluf(acc2a[0]), siluf(acc2a[1]));
                    frag[2 * ct2].y     = h2u(siluf(acc2a[2]), siluf(acc2a[3]));
                    frag[2 * ct2 + 1].x = h2u(siluf(acc2b[0]), siluf(acc2b[1]));
                    frag[2 * ct2 + 1].y = h2u(siluf(acc2b[2]), siluf(acc2b[3]));
                }
                // main GEMM k-steps for this half (k16 steps 4hf..4hf+3)
#pragma unroll
                for (int ks2 = 0; ks2 < 4; ks2++) {
                    const uint32_t a0 = frag[2 * ks2].x;
                    const uint32_t a1 = frag[2 * ks2].y;
                    const uint32_t a2 = frag[2 * ks2 + 1].x;
                    const uint32_t a3 = frag[2 * ks2 + 1].y;
                    const int ks = 4 * hf + ks2;
#pragma unroll
                    for (int ct = 0; ct < 8; ct++) {
                        const uint2 B = g_WfragEh[(ks * 8 + ct) * 32 + lane];
                        mma_f16(acc[ct], a0, a1, a2, a3, B.x, B.y);
                    }
                }
            }

            // ---- epilogue: silu(acc + be2) * attn -> red scatter ----
#pragma unroll
            for (int h = 0; h < 2; h++) {
                const int eL = rA + 8 * h;
                if (base + eL < E) {
                    const float at = __uint_as_float(attn[eL]);
                    float* aggp = g_agg + (long long)(int)fi[eL] * DOUT;
#pragma unroll
                    for (int ct = 0; ct < 8; ct++) {
                        const int col = 8 * ct + 2 * (lane & 3);
                        red_add_v2(aggp + col,
                                   siluf(acc[ct][2 * h + 0] + bb[ct].x) * at,
                                   siluf(acc[ct][2 * h + 1] + bb[ct].y) * at);
                    }
                }
            }
            __threadfence_block();
            BAR_ARRIVE(3 + b);
        }
    }
}

// ---------------------------------------------------------------- node MLP: tf32 MMA
#define NT 64
#define NSTRIDE 132
__global__ __launch_bounds__(256) void node_kernel(
    const float* __restrict__ X, const float* __restrict__ bn1,
    const float* __restrict__ bn2, float* __restrict__ out, int N)
{
    __shared__ uint32_t in_sh[NT][NSTRIDE];
    __shared__ uint32_t hid_sh[NT][NSTRIDE];
    const int tid  = threadIdx.x;
    const int lane = tid & 31;
    const int warp = tid >> 5;
    const int nb   = blockIdx.x * NT;

    for (int i = tid; i < NT * 32; i += 256) {
        const int r = i >> 5, c = i & 31;
        const int n = nb + r;
        float4 v = make_float4(0.f, 0.f, 0.f, 0.f);
        if (n < N) {
            v = (c < 16) ? ((const float4*)X)[(long long)n * 16 + c]
                         : ((const float4*)g_agg)[(long long)n * 16 + (c - 16)];
        }
        uint4 u;
        u.x = tf32b(v.x); u.y = tf32b(v.y); u.z = tf32b(v.z); u.w = tf32b(v.w);
        *(uint4*)&in_sh[r][4 * c] = u;
    }
    __syncthreads();

    const int rg   = warp >> 1;
    const int half = warp & 1;
    const int r0   = 16 * rg;
    const int rA   = r0 + (lane >> 2);

    float acc[8][4];
#pragma unroll
    for (int ct = 0; ct < 8; ct++)
#pragma unroll
        for (int u = 0; u < 4; u++) acc[ct][u] = 0.f;

#pragma unroll
    for (int ks = 0; ks < 16; ks++) {
        const int acol = 8 * ks + (lane & 3);
        const uint32_t a0 = in_sh[rA][acol];
        const uint32_t a1 = in_sh[rA + 8][acol];
        const uint32_t a2 = in_sh[rA][acol + 4];
        const uint32_t a3 = in_sh[rA + 8][acol + 4];
#pragma unroll
        for (int ct = 0; ct < 8; ct++) {
            const uint2 B = g_WfragN1[(ks * 16 + 8 * half + ct) * 32 + lane];
            mma_tf32(acc[ct], a0, a1, a2, a3, B.x, B.y);
        }
    }
#pragma unroll
    for (int ct = 0; ct < 8; ct++) {
        const int col = 8 * (8 * half + ct) + 2 * (lane & 3);
        const float2 b1 = *(const float2*)(bn1 + col);
        uint2 u0, u1;
        u0.x = tf32b(siluf(acc[ct][0] + b1.x));
        u0.y = tf32b(siluf(acc[ct][1] + b1.y));
        u1.x = tf32b(siluf(acc[ct][2] + b1.x));
        u1.y = tf32b(siluf(acc[ct][3] + b1.y));
        *(uint2*)&hid_sh[rA][col] = u0;
        *(uint2*)&hid_sh[rA + 8][col] = u1;
    }
    __syncthreads();

    float acc2[4][4];
#pragma unroll
    for (int ct = 0; ct < 4; ct++)
#pragma unroll
        for (int u = 0; u < 4; u++) acc2[ct][u] = 0.f;

#pragma unroll
    for (int ks = 0; ks < 16; ks++) {
        const int acol = 8 * ks + (lane & 3);
        const uint32_t a0 = hid_sh[rA][acol];
        const uint32_t a1 = hid_sh[rA + 8][acol];
        const uint32_t a2 = hid_sh[rA][acol + 4];
        const uint32_t a3 = hid_sh[rA + 8][acol + 4];
#pragma unroll
        for (int ct = 0; ct < 4; ct++) {
            const uint2 B = g_WfragN2[(ks * 8 + 4 * half + ct) * 32 + lane];
            mma_tf32(acc2[ct], a0, a1, a2, a3, B.x, B.y);
        }
    }
#pragma unroll
    for (int ct = 0; ct < 4; ct++) {
        const int col = 8 * (4 * half + ct) + 2 * (lane & 3);
        const float2 b2 = *(const float2*)(bn2 + col);
#pragma unroll
        for (int h = 0; h < 2; h++) {
            const int n = nb + rA + 8 * h;
            if (n < N) {
                float2 o;
                o.x = acc2[ct][2 * h + 0] + b2.x;
                o.y = acc2[ct][2 * h + 1] + b2.y;
                *(float2*)(out + (long long)n * DOUT + col) = o;
            }
        }
    }
}

// ---------------------------------------------------------------- tail copies
__global__ void tail_kernel(const int* __restrict__ ei,
                            const float* __restrict__ EF,
                            float* __restrict__ out,
                            long long offEI, long long nEI, long long nEF)
{
    const long long tid4 = (long long)blockIdx.x * blockDim.x + threadIdx.x;
    const long long stride = (long long)gridDim.x * blockDim.x;

    const long long nEI4 = nEI >> 2;
    const int4* ei4 = (const int4*)ei;
    for (long long i = tid4; i < nEI4; i += stride) {
        const int4 v = ei4[i];
        float4 f;
        f.x = (float)v.x; f.y = (float)v.y; f.z = (float)v.z; f.w = (float)v.w;
        *(float4*)(out + offEI + 4 * i) = f;
    }
    for (long long i = nEI4 * 4 + tid4; i < nEI; i += stride)
        out[offEI + i] = (float)ei[i];

    const long long offEF = offEI + nEI;
    const long long nEF4 = nEF >> 2;
    const float4* EF4 = (const float4*)EF;
    for (long long i = tid4; i < nEF4; i += stride)
        *(float4*)(out + offEF + 4 * i) = EF4[i];
    for (long long i = nEF4 * 4 + tid4; i < nEF; i += stride)
        out[offEF + i] = EF[i];
}

// ---------------------------------------------------------------- launch
extern "C" void kernel_launch(void* const* d_in, const int* in_sizes, int n_in,
                              void* d_out, int out_size)
{
    const float* X   = (const float*)d_in[0];
    const int*   ei  = (const int*)d_in[1];
    const float* EF  = (const float*)d_in[2];
    const float* We1 = (const float*)d_in[3];
    const float* be1 = (const float*)d_in[4];
    const float* We2 = (const float*)d_in[5];
    const float* be2 = (const float*)d_in[6];
    const float* Wa  = (const float*)d_in[7];
    const float* ba  = (const float*)d_in[8];
    const float* Wn1 = (const float*)d_in[9];
    const float* bn1 = (const float*)d_in[10];
    const float* Wn2 = (const float*)d_in[11];
    const float* bn2 = (const float*)d_in[12];

    const int N = in_sizes[0] / D;
    const int E = in_sizes[2] / DE;
    float* out = (float*)d_out;

    static int smem_set = 0;
    if (!smem_set) {
        cudaFuncSetAttribute(edge_kernel,
                             cudaFuncAttributeMaxDynamicSharedMemorySize, EDGE_SMEM);
        smem_set = 1;
    }

    setup_kernel<<<58, 256>>>(We1, We2, Wn1, Wn2);
    zero_agg_kernel<<<512, 256>>>(((long long)N * DOUT) / 4);
    precompute_kernel<<<(N + PNODES - 1) / PNODES, 128>>>(X, We1, be1, N);

    const int numTiles = (E + TE - 1) / TE;
    int grid = 444;
    if (grid > numTiles) grid = numTiles;
    edge_kernel<<<grid, 256, EDGE_SMEM>>>(ei, EF, Wa, ba, be2, N, E);

    node_kernel<<<(N + NT - 1) / NT, 256>>>(X, bn1, bn2, out, N);

    const long long n64 = (long long)N * DOUT;
    long long avail = (long long)out_size - n64;
    if (avail > 0) {
        long long nEI = 2LL * E;
        if (nEI > avail) nEI = avail;
        long long nEF = avail - nEI;
        const long long maxEF = (long long)E * DE;
        if (nEF > maxEF) nEF = maxEF;
        tail_kernel<<<2048, 256>>>(ei, EF, out, n64, nEI, nEF);
    }
}